// round 10
// baseline (speedup 1.0000x reference)
#include <cuda_runtime.h>
#include <cuda_fp16.h>
#include <cstdint>

#define NMAX   100096
#define EMAX   1600000
#define INF_   128
#define OC_    128
#define HEADS_ 4
#define OUTF_  32
#define NEG_SLOPE_ 0.2f

// ---------------- scratch ----------------
__device__ __half g_WhH[(size_t)NMAX * OC_];    // 25.6 MB (want L2-resident)
__device__ float g_ssrc[(size_t)NMAX * HEADS_];
__device__ float g_sdst[(size_t)NMAX * HEADS_];
__device__ float g_attn[(size_t)NMAX * HEADS_]; // unnormalized exp(nscore)
__device__ float g_gsum[HEADS_];
__device__ int   g_deg[NMAX];
__device__ int   g_incl[NMAX];
__device__ int   g_rowptr[NMAX];
__device__ int   g_cursor[NMAX];
__device__ int   g_esrc[EMAX];
__device__ int   g_bsum[128];
__device__ int   g_boff[128];

__device__ __forceinline__ float neg_inf() { return __int_as_float(0xFF800000); }

__device__ __forceinline__ float to_tf32(float x) {
    float r;
    asm("cvt.rna.tf32.f32 %0, %1;" : "=f"(r) : "f"(x));
    return r;
}

__device__ __forceinline__ void mma_tf32(float* c, const uint32_t* a, const uint32_t* b) {
    asm volatile(
        "mma.sync.aligned.m16n8k8.row.col.f32.tf32.tf32.f32 "
        "{%0,%1,%2,%3},{%4,%5,%6,%7},{%8,%9},{%0,%1,%2,%3};"
        : "+f"(c[0]), "+f"(c[1]), "+f"(c[2]), "+f"(c[3])
        : "r"(a[0]), "r"(a[1]), "r"(a[2]), "r"(a[3]), "r"(b[0]), "r"(b[1]));
}

// ---------------- init: zero deg, reset global sums ------------------------
__global__ void init_kernel(int N) {
    int i = blockIdx.x * blockDim.x + threadIdx.x;
    if (i < N) g_deg[i] = 0;
    if (i == 0) {
        #pragma unroll
        for (int h = 0; h < HEADS_; h++) g_gsum[h] = 0.f;
    }
}

// ---------------- degree histogram (4 edges per thread) --------------------
__global__ void count_kernel(const int* __restrict__ ei, int E) {
    int t = blockIdx.x * blockDim.x + threadIdx.x;
    int base = t * 4;
    if (base + 3 < E) {
        int4 d = *(const int4*)(ei + E + base);
        atomicAdd(&g_deg[d.x], 1); atomicAdd(&g_deg[d.y], 1);
        atomicAdd(&g_deg[d.z], 1); atomicAdd(&g_deg[d.w], 1);
    } else {
        for (int e = base; e < E; e++) atomicAdd(&g_deg[ei[E + e]], 1);
    }
}

// ---------------- 3-phase exclusive scan of degrees ------------------------
__global__ void scan1_kernel(int N) {
    __shared__ int s[1024];
    int tid = threadIdx.x;
    int i = blockIdx.x * 1024 + tid;
    s[tid] = (i < N) ? g_deg[i] : 0;
    __syncthreads();
    for (int o = 1; o < 1024; o <<= 1) {
        int t = (tid >= o) ? s[tid - o] : 0;
        __syncthreads();
        s[tid] += t;
        __syncthreads();
    }
    if (i < N) g_incl[i] = s[tid];
    if (tid == 1023) g_bsum[blockIdx.x] = s[1023];
}

// parallel scan of up to 128 block sums
__global__ void scan2_kernel(int nb) {
    __shared__ int wsum[4], woff[4];
    int tid = threadIdx.x;
    int lane = tid & 31, w = tid >> 5;
    int v = (tid < nb) ? g_bsum[tid] : 0;
    int x = v;
    #pragma unroll
    for (int o = 1; o < 32; o <<= 1) {
        int y = __shfl_up_sync(0xFFFFFFFFu, x, o);
        if (lane >= o) x += y;
    }
    if (lane == 31) wsum[w] = x;
    __syncthreads();
    if (tid == 0) {
        int acc = 0;
        #pragma unroll
        for (int i = 0; i < 4; i++) { woff[i] = acc; acc += wsum[i]; }
    }
    __syncthreads();
    if (tid < nb) g_boff[tid] = x - v + woff[w];
}

__global__ void scan3_kernel(int N) {
    int i = blockIdx.x * blockDim.x + threadIdx.x;
    if (i >= N) return;
    int start = g_incl[i] - g_deg[i] + g_boff[i >> 10];
    g_rowptr[i] = start;
    g_cursor[i] = start;
}

// ---------------- scatter src ids into CSR order ---------------------------
__global__ void scatter_kernel(const int* __restrict__ ei, int E) {
    int e = blockIdx.x * blockDim.x + threadIdx.x;
    if (e >= E) return;
    int src = ei[e];
    int dst = ei[E + e];
    int pos = atomicAdd(&g_cursor[dst], 1);
    g_esrc[pos] = src;
}

// ---------------- 3xTF32 MMA GEMM + fused scores; Wh stored fp16 -----------
__global__ __launch_bounds__(256) void gemm_kernel(
    const float* __restrict__ A, const float* __restrict__ B,
    const float* __restrict__ av_g, int N)
{
    __shared__ float AsH[16][136];
    __shared__ float AsL[16][136];
    __shared__ float BsH[16][136];
    __shared__ float BsL[16][136];
    __shared__ float sA[256];       // attention vector a: [head][src32|dst32]

    int tid = threadIdx.x;
    int lane = tid & 31, wid = tid >> 5;
    int g = lane >> 2, t = lane & 3;
    int wm = (wid & 3) * 32;
    int wn = (wid >> 2) * 64;
    int br = blockIdx.x * 128;

    sA[tid] = av_g[tid];

    int arow = tid >> 1;
    int akofs = (tid & 1) * 8;
    int bk = tid >> 4;
    int bn = (tid & 15) * 8;

    float c[2][8][4];
    #pragma unroll
    for (int mt = 0; mt < 2; mt++)
        #pragma unroll
        for (int nt = 0; nt < 8; nt++)
            #pragma unroll
            for (int q = 0; q < 4; q++) c[mt][nt][q] = 0.f;

    for (int k0 = 0; k0 < INF_; k0 += 16) {
        float av[8] = {};
        int grow = br + arow;
        if (grow < N) {
            float4 a0 = *(const float4*)(A + (size_t)grow * INF_ + k0 + akofs);
            float4 a1 = *(const float4*)(A + (size_t)grow * INF_ + k0 + akofs + 4);
            av[0] = a0.x; av[1] = a0.y; av[2] = a0.z; av[3] = a0.w;
            av[4] = a1.x; av[5] = a1.y; av[6] = a1.z; av[7] = a1.w;
        }
        #pragma unroll
        for (int q = 0; q < 8; q++) {
            float hi = to_tf32(av[q]);
            AsH[akofs + q][arow] = hi;
            AsL[akofs + q][arow] = to_tf32(av[q] - hi);
        }

        float4 b0 = *(const float4*)(B + (size_t)(k0 + bk) * OC_ + bn);
        float4 b1 = *(const float4*)(B + (size_t)(k0 + bk) * OC_ + bn + 4);
        float bv[8] = { b0.x, b0.y, b0.z, b0.w, b1.x, b1.y, b1.z, b1.w };
        #pragma unroll
        for (int q = 0; q < 8; q++) {
            float hi = to_tf32(bv[q]);
            BsH[bk][bn + q] = hi;
            BsL[bk][bn + q] = to_tf32(bv[q] - hi);
        }

        __syncthreads();
        #pragma unroll
        for (int kk = 0; kk < 16; kk += 8) {
            uint32_t afh[2][4], afl[2][4];
            #pragma unroll
            for (int mt = 0; mt < 2; mt++) {
                int m = wm + mt * 16;
                afh[mt][0] = __float_as_uint(AsH[kk + t][m + g]);
                afh[mt][1] = __float_as_uint(AsH[kk + t][m + g + 8]);
                afh[mt][2] = __float_as_uint(AsH[kk + 4 + t][m + g]);
                afh[mt][3] = __float_as_uint(AsH[kk + 4 + t][m + g + 8]);
                afl[mt][0] = __float_as_uint(AsL[kk + t][m + g]);
                afl[mt][1] = __float_as_uint(AsL[kk + t][m + g + 8]);
                afl[mt][2] = __float_as_uint(AsL[kk + 4 + t][m + g]);
                afl[mt][3] = __float_as_uint(AsL[kk + 4 + t][m + g + 8]);
            }
            #pragma unroll
            for (int nt = 0; nt < 8; nt++) {
                int n = wn + nt * 8 + g;
                uint32_t bfh[2], bfl[2];
                bfh[0] = __float_as_uint(BsH[kk + t][n]);
                bfh[1] = __float_as_uint(BsH[kk + 4 + t][n]);
                bfl[0] = __float_as_uint(BsL[kk + t][n]);
                bfl[1] = __float_as_uint(BsL[kk + 4 + t][n]);
                #pragma unroll
                for (int mt = 0; mt < 2; mt++) {
                    mma_tf32(c[mt][nt], afl[mt], bfh);   // lo*hi
                    mma_tf32(c[mt][nt], afh[mt], bfl);   // hi*lo
                    mma_tf32(c[mt][nt], afh[mt], bfh);   // hi*hi
                }
            }
        }
        __syncthreads();
    }

    // ---- store Wh as fp16 (only consumer is the aggregate gather) ----
    #pragma unroll
    for (int mt = 0; mt < 2; mt++) {
        #pragma unroll
        for (int nt = 0; nt < 8; nt++) {
            int row0 = br + wm + mt * 16 + g;
            int col = wn + nt * 8 + 2 * t;
            if (row0 < N)
                *(__half2*)(g_WhH + (size_t)row0 * OC_ + col) =
                    __floats2half2_rn(c[mt][nt][0], c[mt][nt][1]);
            int row1 = row0 + 8;
            if (row1 < N)
                *(__half2*)(g_WhH + (size_t)row1 * OC_ + col) =
                    __floats2half2_rn(c[mt][nt][2], c[mt][nt][3]);
        }
    }

    // ---- fused scores from register fragments (fp32) ----
    float ds[2][2][2] = {}, dd[2][2][2] = {};
    #pragma unroll
    for (int nt = 0; nt < 8; nt++) {
        int col0 = wn + nt * 8 + 2 * t;
        int hgl = col0 >> 5;
        int j = col0 & 31;
        float as0 = sA[hgl * 64 + j],      as1 = sA[hgl * 64 + j + 1];
        float ad0 = sA[hgl * 64 + 32 + j], ad1 = sA[hgl * 64 + 33 + j];
        int hh = nt >> 2;
        #pragma unroll
        for (int mt = 0; mt < 2; mt++) {
            ds[mt][0][hh] += c[mt][nt][0] * as0 + c[mt][nt][1] * as1;
            ds[mt][1][hh] += c[mt][nt][2] * as0 + c[mt][nt][3] * as1;
            dd[mt][0][hh] += c[mt][nt][0] * ad0 + c[mt][nt][1] * ad1;
            dd[mt][1][hh] += c[mt][nt][2] * ad0 + c[mt][nt][3] * ad1;
        }
    }
    int hbase = wn >> 5;
    #pragma unroll
    for (int mt = 0; mt < 2; mt++)
        #pragma unroll
        for (int rh = 0; rh < 2; rh++)
            #pragma unroll
            for (int hh = 0; hh < 2; hh++) {
                float vs = ds[mt][rh][hh];
                float vd = dd[mt][rh][hh];
                vs += __shfl_xor_sync(0xFFFFFFFFu, vs, 1);
                vs += __shfl_xor_sync(0xFFFFFFFFu, vs, 2);
                vd += __shfl_xor_sync(0xFFFFFFFFu, vd, 1);
                vd += __shfl_xor_sync(0xFFFFFFFFu, vd, 2);
                if (t == 0) {
                    int row = br + wm + mt * 16 + g + rh * 8;
                    if (row < N) {
                        g_ssrc[row * HEADS_ + hbase + hh] = vs;
                        g_sdst[row * HEADS_ + hbase + hh] = vd;
                    }
                }
            }
}

// ---------------- pull segment-max + leaky + exp + global sum --------------
__global__ __launch_bounds__(256) void nodemax_kernel(int N) {
    __shared__ float ssum[8][4];
    int gw   = (blockIdx.x * blockDim.x + threadIdx.x) >> 5;
    int lane = threadIdx.x & 31;
    int wrp  = threadIdx.x >> 5;
    bool valid = gw < N;

    float ni = neg_inf();
    float e0 = 0.f, e1 = 0.f, e2 = 0.f, e3 = 0.f;
    if (valid) {
        int start = g_rowptr[gw];
        int cnt   = g_deg[gw];
        float m0 = ni, m1 = ni, m2 = ni, m3 = ni;
        for (int i = lane; i < cnt; i += 32) {
            int s = __ldcs(&g_esrc[start + i]);        // streaming: don't cache
            float4 v = *(const float4*)(g_ssrc + (size_t)s * HEADS_);
            m0 = fmaxf(m0, v.x); m1 = fmaxf(m1, v.y);
            m2 = fmaxf(m2, v.z); m3 = fmaxf(m3, v.w);
        }
        #pragma unroll
        for (int o = 16; o >= 1; o >>= 1) {
            m0 = fmaxf(m0, __shfl_xor_sync(0xFFFFFFFFu, m0, o));
            m1 = fmaxf(m1, __shfl_xor_sync(0xFFFFFFFFu, m1, o));
            m2 = fmaxf(m2, __shfl_xor_sync(0xFFFFFFFFu, m2, o));
            m3 = fmaxf(m3, __shfl_xor_sync(0xFFFFFFFFu, m3, o));
        }
        if (lane == 0) {
            float4 sd = *(const float4*)(g_sdst + (size_t)gw * HEADS_);
            float v0 = m0 + sd.x; v0 = v0 > 0.f ? v0 : NEG_SLOPE_ * v0;
            float v1 = m1 + sd.y; v1 = v1 > 0.f ? v1 : NEG_SLOPE_ * v1;
            float v2 = m2 + sd.z; v2 = v2 > 0.f ? v2 : NEG_SLOPE_ * v2;
            float v3 = m3 + sd.w; v3 = v3 > 0.f ? v3 : NEG_SLOPE_ * v3;
            e0 = __expf(v0); e1 = __expf(v1);
            e2 = __expf(v2); e3 = __expf(v3);
            *(float4*)(g_attn + (size_t)gw * HEADS_) = make_float4(e0, e1, e2, e3);
        }
    }
    if (lane == 0) {
        ssum[wrp][0] = e0; ssum[wrp][1] = e1;
        ssum[wrp][2] = e2; ssum[wrp][3] = e3;
    }
    __syncthreads();
    if (threadIdx.x < 4) {
        float s = ssum[0][threadIdx.x];
        #pragma unroll
        for (int w = 1; w < 8; w++) s += ssum[w][threadIdx.x];
        atomicAdd(&g_gsum[threadIdx.x], s);
    }
}

// ---------------- pull aggregation: warp per node, lane-pair edge split ----
// Streaming-policy version: out stores and esrc reads use evict-first (.cs)
// so the 25.6MB Wh gather table stays L2-resident.
__global__ __launch_bounds__(256) void aggregate_kernel(float* __restrict__ out, int N) {
    int gw   = (blockIdx.x * blockDim.x + threadIdx.x) >> 5;
    int lane = threadIdx.x & 31;
    if (gw >= N) return;
    int start = g_rowptr[gw];
    int end   = start + g_deg[gw];

    int half = lane >> 4;       // 0: even edges, 1: odd edges
    int l    = lane & 15;       // column-slice lane
    const __half* whl = g_WhH + l * 8;   // cols [l*8, l*8+8)

    float a0 = 0.f, a1 = 0.f, a2 = 0.f, a3 = 0.f;
    float a4 = 0.f, a5 = 0.f, a6 = 0.f, a7 = 0.f;

    int i = start;
    for (; i + 7 < end; i += 8) {
        int s0 = __ldcs(&g_esrc[i + 0 + half]);
        int s1 = __ldcs(&g_esrc[i + 2 + half]);
        int s2 = __ldcs(&g_esrc[i + 4 + half]);
        int s3 = __ldcs(&g_esrc[i + 6 + half]);
        uint4 u0 = *(const uint4*)(whl + (size_t)s0 * OC_);
        uint4 u1 = *(const uint4*)(whl + (size_t)s1 * OC_);
        uint4 u2 = *(const uint4*)(whl + (size_t)s2 * OC_);
        uint4 u3 = *(const uint4*)(whl + (size_t)s3 * OC_);
        float2 p;
        p = __half22float2(*(__half2*)&u0.x); a0 += p.x; a1 += p.y;
        p = __half22float2(*(__half2*)&u0.y); a2 += p.x; a3 += p.y;
        p = __half22float2(*(__half2*)&u0.z); a4 += p.x; a5 += p.y;
        p = __half22float2(*(__half2*)&u0.w); a6 += p.x; a7 += p.y;
        p = __half22float2(*(__half2*)&u1.x); a0 += p.x; a1 += p.y;
        p = __half22float2(*(__half2*)&u1.y); a2 += p.x; a3 += p.y;
        p = __half22float2(*(__half2*)&u1.z); a4 += p.x; a5 += p.y;
        p = __half22float2(*(__half2*)&u1.w); a6 += p.x; a7 += p.y;
        p = __half22float2(*(__half2*)&u2.x); a0 += p.x; a1 += p.y;
        p = __half22float2(*(__half2*)&u2.y); a2 += p.x; a3 += p.y;
        p = __half22float2(*(__half2*)&u2.z); a4 += p.x; a5 += p.y;
        p = __half22float2(*(__half2*)&u2.w); a6 += p.x; a7 += p.y;
        p = __half22float2(*(__half2*)&u3.x); a0 += p.x; a1 += p.y;
        p = __half22float2(*(__half2*)&u3.y); a2 += p.x; a3 += p.y;
        p = __half22float2(*(__half2*)&u3.z); a4 += p.x; a5 += p.y;
        p = __half22float2(*(__half2*)&u3.w); a6 += p.x; a7 += p.y;
    }
    for (; i + 1 < end; i += 2) {
        int s = __ldcs(&g_esrc[i + half]);
        uint4 u = *(const uint4*)(whl + (size_t)s * OC_);
        float2 p;
        p = __half22float2(*(__half2*)&u.x); a0 += p.x; a1 += p.y;
        p = __half22float2(*(__half2*)&u.y); a2 += p.x; a3 += p.y;
        p = __half22float2(*(__half2*)&u.z); a4 += p.x; a5 += p.y;
        p = __half22float2(*(__half2*)&u.w); a6 += p.x; a7 += p.y;
    }
    if (i < end && half == 0) {   // last odd edge: even-half only
        int s = __ldcs(&g_esrc[i]);
        uint4 u = *(const uint4*)(whl + (size_t)s * OC_);
        float2 p;
        p = __half22float2(*(__half2*)&u.x); a0 += p.x; a1 += p.y;
        p = __half22float2(*(__half2*)&u.y); a2 += p.x; a3 += p.y;
        p = __half22float2(*(__half2*)&u.z); a4 += p.x; a5 += p.y;
        p = __half22float2(*(__half2*)&u.w); a6 += p.x; a7 += p.y;
    }

    // merge even/odd halves (lane L <-> L+16 hold the same columns)
    a0 += __shfl_xor_sync(0xFFFFFFFFu, a0, 16);
    a1 += __shfl_xor_sync(0xFFFFFFFFu, a1, 16);
    a2 += __shfl_xor_sync(0xFFFFFFFFu, a2, 16);
    a3 += __shfl_xor_sync(0xFFFFFFFFu, a3, 16);
    a4 += __shfl_xor_sync(0xFFFFFFFFu, a4, 16);
    a5 += __shfl_xor_sync(0xFFFFFFFFu, a5, 16);
    a6 += __shfl_xor_sync(0xFFFFFFFFu, a6, 16);
    a7 += __shfl_xor_sync(0xFFFFFFFFu, a7, 16);

    int head = l >> 2;
    float attn = g_attn[(size_t)gw * HEADS_ + head] / g_gsum[head];
    if (half == 0) {
        float* op = out + (size_t)gw * OC_ + l * 8;
        __stcs((float4*)op,
               make_float4(a0 * attn, a1 * attn, a2 * attn, a3 * attn));
        __stcs((float4*)(op + 4),
               make_float4(a4 * attn, a5 * attn, a6 * attn, a7 * attn));
    }
}

// ---------------- launch: R7 topology -------------------------------------
extern "C" void kernel_launch(void* const* d_in, const int* in_sizes, int n_in,
                              void* d_out, int out_size) {
    const float* h  = (const float*)d_in[0];
    const int*   ei = (const int*)d_in[1];
    const float* W  = (const float*)d_in[2];
    const float* a  = (const float*)d_in[3];
    float* out = (float*)d_out;

    int N = in_sizes[0] / INF_;
    int E = in_sizes[1] / 2;
    int nb = (N + 1023) / 1024;

    static cudaStream_t s2 = nullptr;
    static cudaEvent_t e0 = nullptr, e2 = nullptr;
    if (s2 == nullptr) {
        cudaStreamCreateWithFlags(&s2, cudaStreamNonBlocking);
        cudaEventCreateWithFlags(&e0, cudaEventDisableTiming);
        cudaEventCreateWithFlags(&e2, cudaEventDisableTiming);
    }

    // fork: CSR build chain on s2, GEMM (+fused scores) on the main stream
    cudaEventRecord(e0, 0);
    cudaStreamWaitEvent(s2, e0, 0);

    init_kernel<<<(N + 255) / 256, 256, 0, s2>>>(N);
    count_kernel<<<((E + 3) / 4 + 255) / 256, 256, 0, s2>>>(ei, E);
    scan1_kernel<<<nb, 1024, 0, s2>>>(N);
    scan2_kernel<<<1, 128, 0, s2>>>(nb);
    scan3_kernel<<<(N + 255) / 256, 256, 0, s2>>>(N);
    scatter_kernel<<<(E + 255) / 256, 256, 0, s2>>>(ei, E);
    cudaEventRecord(e2, s2);

    gemm_kernel<<<(N + 127) / 128, 256>>>(h, W, a, N);

    // join: nodemax needs CSR + scores
    cudaStreamWaitEvent(0, e2, 0);

    nodemax_kernel<<<(N * 32 + 255) / 256, 256>>>(N);
    aggregate_kernel<<<(N * 32 + 255) / 256, 256>>>(out, N);
}

// round 11
// speedup vs baseline: 1.0127x; 1.0127x over previous
#include <cuda_runtime.h>
#include <cuda_fp16.h>
#include <cstdint>

#define NMAX   100096
#define EMAX   1600000
#define INF_   128
#define OC_    128
#define HEADS_ 4
#define OUTF_  32
#define NEG_SLOPE_ 0.2f

// ---------------- scratch ----------------
__device__ __half g_WhH[(size_t)NMAX * OC_];    // 25.6 MB (L2-resident)
__device__ float g_ssrc[(size_t)NMAX * HEADS_];
__device__ float g_sdst[(size_t)NMAX * HEADS_];
__device__ float g_attn[(size_t)NMAX * HEADS_]; // unnormalized exp(nscore)
__device__ float g_gsum[HEADS_];
__device__ int   g_deg[NMAX];
__device__ int   g_incl[NMAX];
__device__ int   g_rowptr[NMAX];
__device__ int   g_cursor[NMAX];
__device__ int   g_esrc[EMAX];
__device__ int   g_bsum[128];
__device__ int   g_boff[128];

__device__ __forceinline__ float neg_inf() { return __int_as_float(0xFF800000); }

__device__ __forceinline__ float to_tf32(float x) {
    float r;
    asm("cvt.rna.tf32.f32 %0, %1;" : "=f"(r) : "f"(x));
    return r;
}

__device__ __forceinline__ void mma_tf32(float* c, const uint32_t* a, const uint32_t* b) {
    asm volatile(
        "mma.sync.aligned.m16n8k8.row.col.f32.tf32.tf32.f32 "
        "{%0,%1,%2,%3},{%4,%5,%6,%7},{%8,%9},{%0,%1,%2,%3};"
        : "+f"(c[0]), "+f"(c[1]), "+f"(c[2]), "+f"(c[3])
        : "r"(a[0]), "r"(a[1]), "r"(a[2]), "r"(a[3]), "r"(b[0]), "r"(b[1]));
}

// ---------------- init: zero deg, reset global sums ------------------------
__global__ void init_kernel(int N) {
    int i = blockIdx.x * blockDim.x + threadIdx.x;
    if (i < N) g_deg[i] = 0;
    if (i == 0) {
        #pragma unroll
        for (int h = 0; h < HEADS_; h++) g_gsum[h] = 0.f;
    }
}

// ---------------- degree histogram (4 edges per thread) --------------------
__global__ void count_kernel(const int* __restrict__ ei, int E) {
    int t = blockIdx.x * blockDim.x + threadIdx.x;
    int base = t * 4;
    if (base + 3 < E) {
        int4 d = *(const int4*)(ei + E + base);
        atomicAdd(&g_deg[d.x], 1); atomicAdd(&g_deg[d.y], 1);
        atomicAdd(&g_deg[d.z], 1); atomicAdd(&g_deg[d.w], 1);
    } else {
        for (int e = base; e < E; e++) atomicAdd(&g_deg[ei[E + e]], 1);
    }
}

// ---------------- 3-phase exclusive scan of degrees ------------------------
__global__ void scan1_kernel(int N) {
    __shared__ int s[1024];
    int tid = threadIdx.x;
    int i = blockIdx.x * 1024 + tid;
    s[tid] = (i < N) ? g_deg[i] : 0;
    __syncthreads();
    for (int o = 1; o < 1024; o <<= 1) {
        int t = (tid >= o) ? s[tid - o] : 0;
        __syncthreads();
        s[tid] += t;
        __syncthreads();
    }
    if (i < N) g_incl[i] = s[tid];
    if (tid == 1023) g_bsum[blockIdx.x] = s[1023];
}

// parallel scan of up to 128 block sums
__global__ void scan2_kernel(int nb) {
    __shared__ int wsum[4], woff[4];
    int tid = threadIdx.x;
    int lane = tid & 31, w = tid >> 5;
    int v = (tid < nb) ? g_bsum[tid] : 0;
    int x = v;
    #pragma unroll
    for (int o = 1; o < 32; o <<= 1) {
        int y = __shfl_up_sync(0xFFFFFFFFu, x, o);
        if (lane >= o) x += y;
    }
    if (lane == 31) wsum[w] = x;
    __syncthreads();
    if (tid == 0) {
        int acc = 0;
        #pragma unroll
        for (int i = 0; i < 4; i++) { woff[i] = acc; acc += wsum[i]; }
    }
    __syncthreads();
    if (tid < nb) g_boff[tid] = x - v + woff[w];
}

__global__ void scan3_kernel(int N) {
    int i = blockIdx.x * blockDim.x + threadIdx.x;
    if (i >= N) return;
    int start = g_incl[i] - g_deg[i] + g_boff[i >> 10];
    g_rowptr[i] = start;
    g_cursor[i] = start;
}

// ---------------- scatter src ids into CSR order ---------------------------
__global__ void scatter_kernel(const int* __restrict__ ei, int E) {
    int e = blockIdx.x * blockDim.x + threadIdx.x;
    if (e >= E) return;
    int src = ei[e];
    int dst = ei[E + e];
    int pos = atomicAdd(&g_cursor[dst], 1);
    g_esrc[pos] = src;
}

// ---------------- 3xTF32 MMA GEMM + fused scores; Wh stored fp16 -----------
__global__ __launch_bounds__(256) void gemm_kernel(
    const float* __restrict__ A, const float* __restrict__ B,
    const float* __restrict__ av_g, int N)
{
    __shared__ float AsH[16][136];
    __shared__ float AsL[16][136];
    __shared__ float BsH[16][136];
    __shared__ float BsL[16][136];
    __shared__ float sA[256];       // attention vector a: [head][src32|dst32]

    int tid = threadIdx.x;
    int lane = tid & 31, wid = tid >> 5;
    int g = lane >> 2, t = lane & 3;
    int wm = (wid & 3) * 32;
    int wn = (wid >> 2) * 64;
    int br = blockIdx.x * 128;

    sA[tid] = av_g[tid];

    int arow = tid >> 1;
    int akofs = (tid & 1) * 8;
    int bk = tid >> 4;
    int bn = (tid & 15) * 8;

    float c[2][8][4];
    #pragma unroll
    for (int mt = 0; mt < 2; mt++)
        #pragma unroll
        for (int nt = 0; nt < 8; nt++)
            #pragma unroll
            for (int q = 0; q < 4; q++) c[mt][nt][q] = 0.f;

    for (int k0 = 0; k0 < INF_; k0 += 16) {
        float av[8] = {};
        int grow = br + arow;
        if (grow < N) {
            float4 a0 = *(const float4*)(A + (size_t)grow * INF_ + k0 + akofs);
            float4 a1 = *(const float4*)(A + (size_t)grow * INF_ + k0 + akofs + 4);
            av[0] = a0.x; av[1] = a0.y; av[2] = a0.z; av[3] = a0.w;
            av[4] = a1.x; av[5] = a1.y; av[6] = a1.z; av[7] = a1.w;
        }
        #pragma unroll
        for (int q = 0; q < 8; q++) {
            float hi = to_tf32(av[q]);
            AsH[akofs + q][arow] = hi;
            AsL[akofs + q][arow] = to_tf32(av[q] - hi);
        }

        float4 b0 = *(const float4*)(B + (size_t)(k0 + bk) * OC_ + bn);
        float4 b1 = *(const float4*)(B + (size_t)(k0 + bk) * OC_ + bn + 4);
        float bv[8] = { b0.x, b0.y, b0.z, b0.w, b1.x, b1.y, b1.z, b1.w };
        #pragma unroll
        for (int q = 0; q < 8; q++) {
            float hi = to_tf32(bv[q]);
            BsH[bk][bn + q] = hi;
            BsL[bk][bn + q] = to_tf32(bv[q] - hi);
        }

        __syncthreads();
        #pragma unroll
        for (int kk = 0; kk < 16; kk += 8) {
            uint32_t afh[2][4], afl[2][4];
            #pragma unroll
            for (int mt = 0; mt < 2; mt++) {
                int m = wm + mt * 16;
                afh[mt][0] = __float_as_uint(AsH[kk + t][m + g]);
                afh[mt][1] = __float_as_uint(AsH[kk + t][m + g + 8]);
                afh[mt][2] = __float_as_uint(AsH[kk + 4 + t][m + g]);
                afh[mt][3] = __float_as_uint(AsH[kk + 4 + t][m + g + 8]);
                afl[mt][0] = __float_as_uint(AsL[kk + t][m + g]);
                afl[mt][1] = __float_as_uint(AsL[kk + t][m + g + 8]);
                afl[mt][2] = __float_as_uint(AsL[kk + 4 + t][m + g]);
                afl[mt][3] = __float_as_uint(AsL[kk + 4 + t][m + g + 8]);
            }
            #pragma unroll
            for (int nt = 0; nt < 8; nt++) {
                int n = wn + nt * 8 + g;
                uint32_t bfh[2], bfl[2];
                bfh[0] = __float_as_uint(BsH[kk + t][n]);
                bfh[1] = __float_as_uint(BsH[kk + 4 + t][n]);
                bfl[0] = __float_as_uint(BsL[kk + t][n]);
                bfl[1] = __float_as_uint(BsL[kk + 4 + t][n]);
                #pragma unroll
                for (int mt = 0; mt < 2; mt++) {
                    mma_tf32(c[mt][nt], afl[mt], bfh);   // lo*hi
                    mma_tf32(c[mt][nt], afh[mt], bfl);   // hi*lo
                    mma_tf32(c[mt][nt], afh[mt], bfh);   // hi*hi
                }
            }
        }
        __syncthreads();
    }

    // ---- store Wh as fp16 (only consumer is the aggregate gather) ----
    #pragma unroll
    for (int mt = 0; mt < 2; mt++) {
        #pragma unroll
        for (int nt = 0; nt < 8; nt++) {
            int row0 = br + wm + mt * 16 + g;
            int col = wn + nt * 8 + 2 * t;
            if (row0 < N)
                *(__half2*)(g_WhH + (size_t)row0 * OC_ + col) =
                    __floats2half2_rn(c[mt][nt][0], c[mt][nt][1]);
            int row1 = row0 + 8;
            if (row1 < N)
                *(__half2*)(g_WhH + (size_t)row1 * OC_ + col) =
                    __floats2half2_rn(c[mt][nt][2], c[mt][nt][3]);
        }
    }

    // ---- fused scores from register fragments (fp32) ----
    float ds[2][2][2] = {}, dd[2][2][2] = {};
    #pragma unroll
    for (int nt = 0; nt < 8; nt++) {
        int col0 = wn + nt * 8 + 2 * t;
        int hgl = col0 >> 5;
        int j = col0 & 31;
        float as0 = sA[hgl * 64 + j],      as1 = sA[hgl * 64 + j + 1];
        float ad0 = sA[hgl * 64 + 32 + j], ad1 = sA[hgl * 64 + 33 + j];
        int hh = nt >> 2;
        #pragma unroll
        for (int mt = 0; mt < 2; mt++) {
            ds[mt][0][hh] += c[mt][nt][0] * as0 + c[mt][nt][1] * as1;
            ds[mt][1][hh] += c[mt][nt][2] * as0 + c[mt][nt][3] * as1;
            dd[mt][0][hh] += c[mt][nt][0] * ad0 + c[mt][nt][1] * ad1;
            dd[mt][1][hh] += c[mt][nt][2] * ad0 + c[mt][nt][3] * ad1;
        }
    }
    int hbase = wn >> 5;
    #pragma unroll
    for (int mt = 0; mt < 2; mt++)
        #pragma unroll
        for (int rh = 0; rh < 2; rh++)
            #pragma unroll
            for (int hh = 0; hh < 2; hh++) {
                float vs = ds[mt][rh][hh];
                float vd = dd[mt][rh][hh];
                vs += __shfl_xor_sync(0xFFFFFFFFu, vs, 1);
                vs += __shfl_xor_sync(0xFFFFFFFFu, vs, 2);
                vd += __shfl_xor_sync(0xFFFFFFFFu, vd, 1);
                vd += __shfl_xor_sync(0xFFFFFFFFu, vd, 2);
                if (t == 0) {
                    int row = br + wm + mt * 16 + g + rh * 8;
                    if (row < N) {
                        g_ssrc[row * HEADS_ + hbase + hh] = vs;
                        g_sdst[row * HEADS_ + hbase + hh] = vd;
                    }
                }
            }
}

// ---------------- pull segment-max + leaky + exp + global sum --------------
__global__ __launch_bounds__(256) void nodemax_kernel(int N) {
    __shared__ float ssum[8][4];
    int gw   = (blockIdx.x * blockDim.x + threadIdx.x) >> 5;
    int lane = threadIdx.x & 31;
    int wrp  = threadIdx.x >> 5;
    bool valid = gw < N;

    float ni = neg_inf();
    float e0 = 0.f, e1 = 0.f, e2 = 0.f, e3 = 0.f;
    if (valid) {
        int start = g_rowptr[gw];
        int cnt   = g_deg[gw];
        float m0 = ni, m1 = ni, m2 = ni, m3 = ni;
        for (int i = lane; i < cnt; i += 32) {
            int s = g_esrc[start + i];
            float4 v = *(const float4*)(g_ssrc + (size_t)s * HEADS_);
            m0 = fmaxf(m0, v.x); m1 = fmaxf(m1, v.y);
            m2 = fmaxf(m2, v.z); m3 = fmaxf(m3, v.w);
        }
        #pragma unroll
        for (int o = 16; o >= 1; o >>= 1) {
            m0 = fmaxf(m0, __shfl_xor_sync(0xFFFFFFFFu, m0, o));
            m1 = fmaxf(m1, __shfl_xor_sync(0xFFFFFFFFu, m1, o));
            m2 = fmaxf(m2, __shfl_xor_sync(0xFFFFFFFFu, m2, o));
            m3 = fmaxf(m3, __shfl_xor_sync(0xFFFFFFFFu, m3, o));
        }
        if (lane == 0) {
            float4 sd = *(const float4*)(g_sdst + (size_t)gw * HEADS_);
            float v0 = m0 + sd.x; v0 = v0 > 0.f ? v0 : NEG_SLOPE_ * v0;
            float v1 = m1 + sd.y; v1 = v1 > 0.f ? v1 : NEG_SLOPE_ * v1;
            float v2 = m2 + sd.z; v2 = v2 > 0.f ? v2 : NEG_SLOPE_ * v2;
            float v3 = m3 + sd.w; v3 = v3 > 0.f ? v3 : NEG_SLOPE_ * v3;
            e0 = __expf(v0); e1 = __expf(v1);
            e2 = __expf(v2); e3 = __expf(v3);
            *(float4*)(g_attn + (size_t)gw * HEADS_) = make_float4(e0, e1, e2, e3);
        }
    }
    if (lane == 0) {
        ssum[wrp][0] = e0; ssum[wrp][1] = e1;
        ssum[wrp][2] = e2; ssum[wrp][3] = e3;
    }
    __syncthreads();
    if (threadIdx.x < 4) {
        float s = ssum[0][threadIdx.x];
        #pragma unroll
        for (int w = 1; w < 8; w++) s += ssum[w][threadIdx.x];
        atomicAdd(&g_gsum[threadIdx.x], s);
    }
}

// ---------------- pull aggregation: shfl-distributed indices ---------------
// Lane L loads esrc[start+L] once (coalesced; covers deg<=32, the common
// case); indices then distributed via shfl, so all Wh gathers issue with
// MLP ~= deg instead of alternating index-load/gather latency round trips.
__global__ __launch_bounds__(256) void aggregate_kernel(float* __restrict__ out, int N) {
    int gw   = (blockIdx.x * blockDim.x + threadIdx.x) >> 5;
    int lane = threadIdx.x & 31;
    if (gw >= N) return;
    int start = g_rowptr[gw];
    int cnt   = g_deg[gw];

    float ax = 0.f, ay = 0.f, az = 0.f, aw = 0.f;
    const __half* whl = g_WhH + lane * 4;   // cols [lane*4, lane*4+4)

    for (int base = 0; base < cnt; base += 32) {
        int n = cnt - base; if (n > 32) n = 32;
        int s = (lane < n) ? g_esrc[start + base + lane] : 0;

        int e = 0;
        for (; e + 3 < n; e += 4) {
            int s0 = __shfl_sync(0xFFFFFFFFu, s, e + 0);
            int s1 = __shfl_sync(0xFFFFFFFFu, s, e + 1);
            int s2 = __shfl_sync(0xFFFFFFFFu, s, e + 2);
            int s3 = __shfl_sync(0xFFFFFFFFu, s, e + 3);
            uint2 u0 = *(const uint2*)(whl + (size_t)s0 * OC_);
            uint2 u1 = *(const uint2*)(whl + (size_t)s1 * OC_);
            uint2 u2 = *(const uint2*)(whl + (size_t)s2 * OC_);
            uint2 u3 = *(const uint2*)(whl + (size_t)s3 * OC_);
            float2 p, q;
            p = __half22float2(*(__half2*)&u0.x); q = __half22float2(*(__half2*)&u0.y);
            ax += p.x; ay += p.y; az += q.x; aw += q.y;
            p = __half22float2(*(__half2*)&u1.x); q = __half22float2(*(__half2*)&u1.y);
            ax += p.x; ay += p.y; az += q.x; aw += q.y;
            p = __half22float2(*(__half2*)&u2.x); q = __half22float2(*(__half2*)&u2.y);
            ax += p.x; ay += p.y; az += q.x; aw += q.y;
            p = __half22float2(*(__half2*)&u3.x); q = __half22float2(*(__half2*)&u3.y);
            ax += p.x; ay += p.y; az += q.x; aw += q.y;
        }
        for (; e < n; e++) {
            int se = __shfl_sync(0xFFFFFFFFu, s, e);
            uint2 u = *(const uint2*)(whl + (size_t)se * OC_);
            float2 p = __half22float2(*(__half2*)&u.x);
            float2 q = __half22float2(*(__half2*)&u.y);
            ax += p.x; ay += p.y; az += q.x; aw += q.y;
        }
    }

    int head = lane >> 3;
    float attn = g_attn[(size_t)gw * HEADS_ + head] / g_gsum[head];
    *(float4*)(out + (size_t)gw * OC_ + lane * 4) =
        make_float4(ax * attn, ay * attn, az * attn, aw * attn);
}

// ---------------- launch: gemm at submission index 3 (ncu -s 5 offset) -----
extern "C" void kernel_launch(void* const* d_in, const int* in_sizes, int n_in,
                              void* d_out, int out_size) {
    const float* h  = (const float*)d_in[0];
    const int*   ei = (const int*)d_in[1];
    const float* W  = (const float*)d_in[2];
    const float* a  = (const float*)d_in[3];
    float* out = (float*)d_out;

    int N = in_sizes[0] / INF_;
    int E = in_sizes[1] / 2;
    int nb = (N + 1023) / 1024;

    static cudaStream_t s2 = nullptr;
    static cudaEvent_t e0 = nullptr, e2 = nullptr;
    if (s2 == nullptr) {
        cudaStreamCreateWithFlags(&s2, cudaStreamNonBlocking);
        cudaEventCreateWithFlags(&e0, cudaEventDisableTiming);
        cudaEventCreateWithFlags(&e2, cudaEventDisableTiming);
    }

    // fork: CSR build chain on s2, GEMM (+fused scores) on the main stream
    cudaEventRecord(e0, 0);
    cudaStreamWaitEvent(s2, e0, 0);

    // submission 0-2 (CSR head on s2)
    init_kernel<<<(N + 255) / 256, 256, 0, s2>>>(N);
    count_kernel<<<((E + 3) / 4 + 255) / 256, 256, 0, s2>>>(ei, E);
    scan1_kernel<<<nb, 1024, 0, s2>>>(N);

    // submission 3: gemm on main (independent of s2; executes immediately)
    gemm_kernel<<<(N + 127) / 128, 256>>>(h, W, a, N);

    // submissions 4-6 (CSR tail on s2; in-stream order preserved)
    scan2_kernel<<<1, 128, 0, s2>>>(nb);
    scan3_kernel<<<(N + 255) / 256, 256, 0, s2>>>(N);
    scatter_kernel<<<(E + 255) / 256, 256, 0, s2>>>(ei, E);
    cudaEventRecord(e2, s2);

    // join: nodemax needs CSR + scores
    cudaStreamWaitEvent(0, e2, 0);

    nodemax_kernel<<<(N * 32 + 255) / 256, 256>>>(N);
    aggregate_kernel<<<(N * 32 + 255) / 256, 256>>>(out, N);
}

// round 12
// speedup vs baseline: 1.2367x; 1.2213x over previous
#include <cuda_runtime.h>
#include <cuda_fp16.h>
#include <cuda_bf16.h>
#include <cstdint>

#define NMAX   100096
#define EMAX   1600000
#define INF_   128
#define OC_    128
#define HEADS_ 4
#define OUTF_  32
#define NEG_SLOPE_ 0.2f

// ---------------- scratch ----------------
__device__ __half g_WhH[(size_t)NMAX * OC_];    // 25.6 MB (L2-resident)
__device__ __nv_bfloat16 g_WbH[128 * 128];      // W hi, [n][k] bf16
__device__ __nv_bfloat16 g_WbL[128 * 128];      // W lo, [n][k] bf16
__device__ float g_ssrc[(size_t)NMAX * HEADS_];
__device__ float g_sdst[(size_t)NMAX * HEADS_];
__device__ float g_attn[(size_t)NMAX * HEADS_]; // unnormalized exp(nscore)
__device__ float g_gsum[HEADS_];
__device__ int   g_deg[NMAX];
__device__ int   g_incl[NMAX];
__device__ int   g_rowptr[NMAX];
__device__ int   g_cursor[NMAX];
__device__ int   g_esrc[EMAX];
__device__ int   g_bsum[128];
__device__ int   g_boff[128];

__device__ __forceinline__ float neg_inf() { return __int_as_float(0xFF800000); }

__device__ __forceinline__ uint32_t pack_bf2(float x, float y) {
    __nv_bfloat162 p = __floats2bfloat162_rn(x, y);   // .x = low half
    return *reinterpret_cast<uint32_t*>(&p);
}

__device__ __forceinline__ void mma_bf16(float* c, const uint32_t* a, const uint32_t* b) {
    asm volatile(
        "mma.sync.aligned.m16n8k16.row.col.f32.bf16.bf16.f32 "
        "{%0,%1,%2,%3},{%4,%5,%6,%7},{%8,%9},{%0,%1,%2,%3};"
        : "+f"(c[0]), "+f"(c[1]), "+f"(c[2]), "+f"(c[3])
        : "r"(a[0]), "r"(a[1]), "r"(a[2]), "r"(a[3]), "r"(b[0]), "r"(b[1]));
}

// ---------------- init: zero deg, reset global sums ------------------------
__global__ void init_kernel(int N) {
    int i = blockIdx.x * blockDim.x + threadIdx.x;
    if (i < N) g_deg[i] = 0;
    if (i == 0) {
        #pragma unroll
        for (int h = 0; h < HEADS_; h++) g_gsum[h] = 0.f;
    }
}

// ---------------- W pre-conversion: fp32 [k][n] -> bf16 hi/lo [n][k] -------
__global__ void wconv_kernel(const float* __restrict__ W) {
    int idx = blockIdx.x * blockDim.x + threadIdx.x;
    if (idx >= 128 * 128) return;
    int k = idx >> 7, n = idx & 127;
    float v = W[idx];
    __nv_bfloat16 hi = __float2bfloat16(v);
    float rem = v - __bfloat162float(hi);
    g_WbH[n * 128 + k] = hi;
    g_WbL[n * 128 + k] = __float2bfloat16(rem);
}

// ---------------- degree histogram (4 edges per thread) --------------------
__global__ void count_kernel(const int* __restrict__ ei, int E) {
    int t = blockIdx.x * blockDim.x + threadIdx.x;
    int base = t * 4;
    if (base + 3 < E) {
        int4 d = *(const int4*)(ei + E + base);
        atomicAdd(&g_deg[d.x], 1); atomicAdd(&g_deg[d.y], 1);
        atomicAdd(&g_deg[d.z], 1); atomicAdd(&g_deg[d.w], 1);
    } else {
        for (int e = base; e < E; e++) atomicAdd(&g_deg[ei[E + e]], 1);
    }
}

// ---------------- 3-phase exclusive scan of degrees ------------------------
__global__ void scan1_kernel(int N) {
    __shared__ int s[1024];
    int tid = threadIdx.x;
    int i = blockIdx.x * 1024 + tid;
    s[tid] = (i < N) ? g_deg[i] : 0;
    __syncthreads();
    for (int o = 1; o < 1024; o <<= 1) {
        int t = (tid >= o) ? s[tid - o] : 0;
        __syncthreads();
        s[tid] += t;
        __syncthreads();
    }
    if (i < N) g_incl[i] = s[tid];
    if (tid == 1023) g_bsum[blockIdx.x] = s[1023];
}

// parallel scan of up to 128 block sums
__global__ void scan2_kernel(int nb) {
    __shared__ int wsum[4], woff[4];
    int tid = threadIdx.x;
    int lane = tid & 31, w = tid >> 5;
    int v = (tid < nb) ? g_bsum[tid] : 0;
    int x = v;
    #pragma unroll
    for (int o = 1; o < 32; o <<= 1) {
        int y = __shfl_up_sync(0xFFFFFFFFu, x, o);
        if (lane >= o) x += y;
    }
    if (lane == 31) wsum[w] = x;
    __syncthreads();
    if (tid == 0) {
        int acc = 0;
        #pragma unroll
        for (int i = 0; i < 4; i++) { woff[i] = acc; acc += wsum[i]; }
    }
    __syncthreads();
    if (tid < nb) g_boff[tid] = x - v + woff[w];
}

__global__ void scan3_kernel(int N) {
    int i = blockIdx.x * blockDim.x + threadIdx.x;
    if (i >= N) return;
    int start = g_incl[i] - g_deg[i] + g_boff[i >> 10];
    g_rowptr[i] = start;
    g_cursor[i] = start;
}

// ---------------- scatter src ids into CSR order ---------------------------
__global__ void scatter_kernel(const int* __restrict__ ei, int E) {
    int e = blockIdx.x * blockDim.x + threadIdx.x;
    if (e >= E) return;
    int src = ei[e];
    int dst = ei[E + e];
    int pos = atomicAdd(&g_cursor[dst], 1);
    g_esrc[pos] = src;
}

// ---------------- 3x bf16 m16n8k16 GEMM + fused scores; Wh stored fp16 -----
// smem rows use 12-word stride: (m*12 + t) mod 32 is conflict-free for the
// fragment-load pattern (8 consecutive rows x t in 0..3).
__global__ __launch_bounds__(256) void gemm_kernel(
    const float* __restrict__ A, const float* __restrict__ av_g, int N)
{
    __shared__ uint32_t AsH[128 * 12];
    __shared__ uint32_t AsL[128 * 12];
    __shared__ uint32_t BsH[128 * 12];
    __shared__ uint32_t BsL[128 * 12];
    __shared__ float sA[256];       // attention vector a: [head][src32|dst32]

    int tid = threadIdx.x;
    int lane = tid & 31, wid = tid >> 5;
    int g = lane >> 2, t = lane & 3;
    int wm = (wid & 3) * 32;
    int wn = (wid >> 2) * 64;
    int br = blockIdx.x * 128;

    sA[tid] = av_g[tid];

    int arow = tid >> 1;            // 0..127
    int ak   = (tid & 1) * 8;       // k offset within 16-tile: 0 or 8
    int bn_  = tid >> 1;            // B n row
    int bkof = (tid & 1) * 8;

    float c[2][8][4];
    #pragma unroll
    for (int mt = 0; mt < 2; mt++)
        #pragma unroll
        for (int nt = 0; nt < 8; nt++)
            #pragma unroll
            for (int q = 0; q < 4; q++) c[mt][nt][q] = 0.f;

    for (int k0 = 0; k0 < INF_; k0 += 16) {
        // ---- A tile: load 8 fp32, split to bf16 hi/lo, store packed ----
        float av[8] = {};
        int grow = br + arow;
        if (grow < N) {
            float4 a0 = *(const float4*)(A + (size_t)grow * INF_ + k0 + ak);
            float4 a1 = *(const float4*)(A + (size_t)grow * INF_ + k0 + ak + 4);
            av[0] = a0.x; av[1] = a0.y; av[2] = a0.z; av[3] = a0.w;
            av[4] = a1.x; av[5] = a1.y; av[6] = a1.z; av[7] = a1.w;
        }
        uint32_t hw[4], lw[4];
        #pragma unroll
        for (int j = 0; j < 4; j++) {
            float x = av[2 * j], y = av[2 * j + 1];
            __nv_bfloat16 xh = __float2bfloat16(x);
            __nv_bfloat16 yh = __float2bfloat16(y);
            float xr = x - __bfloat162float(xh);
            float yr = y - __bfloat162float(yh);
            __nv_bfloat162 ph; ph.x = xh; ph.y = yh;
            hw[j] = *reinterpret_cast<uint32_t*>(&ph);
            lw[j] = pack_bf2(xr, yr);
        }
        *(uint4*)&AsH[arow * 12 + (ak >> 1)] = make_uint4(hw[0], hw[1], hw[2], hw[3]);
        *(uint4*)&AsL[arow * 12 + (ak >> 1)] = make_uint4(lw[0], lw[1], lw[2], lw[3]);

        // ---- B tile: straight copy of pre-converted bf16 [n][k] ----
        uint4 wbh = *(const uint4*)(g_WbH + (size_t)bn_ * 128 + k0 + bkof);
        uint4 wbl = *(const uint4*)(g_WbL + (size_t)bn_ * 128 + k0 + bkof);
        *(uint4*)&BsH[bn_ * 12 + (bkof >> 1)] = wbh;
        *(uint4*)&BsL[bn_ * 12 + (bkof >> 1)] = wbl;

        __syncthreads();

        uint32_t afh[2][4], afl[2][4];
        #pragma unroll
        for (int mt = 0; mt < 2; mt++) {
            int m0 = (wm + mt * 16 + g) * 12;
            int m1 = (wm + mt * 16 + g + 8) * 12;
            afh[mt][0] = AsH[m0 + t];     afh[mt][1] = AsH[m1 + t];
            afh[mt][2] = AsH[m0 + t + 4]; afh[mt][3] = AsH[m1 + t + 4];
            afl[mt][0] = AsL[m0 + t];     afl[mt][1] = AsL[m1 + t];
            afl[mt][2] = AsL[m0 + t + 4]; afl[mt][3] = AsL[m1 + t + 4];
        }
        #pragma unroll
        for (int nt = 0; nt < 8; nt++) {
            int nb = (wn + nt * 8 + g) * 12;
            uint32_t bfh[2], bfl[2];
            bfh[0] = BsH[nb + t]; bfh[1] = BsH[nb + t + 4];
            bfl[0] = BsL[nb + t]; bfl[1] = BsL[nb + t + 4];
            #pragma unroll
            for (int mt = 0; mt < 2; mt++) {
                mma_bf16(c[mt][nt], afl[mt], bfh);   // lo*hi
                mma_bf16(c[mt][nt], afh[mt], bfl);   // hi*lo
                mma_bf16(c[mt][nt], afh[mt], bfh);   // hi*hi
            }
        }
        __syncthreads();
    }

    // ---- store Wh as fp16 (only consumer is the aggregate gather) ----
    #pragma unroll
    for (int mt = 0; mt < 2; mt++) {
        #pragma unroll
        for (int nt = 0; nt < 8; nt++) {
            int row0 = br + wm + mt * 16 + g;
            int col = wn + nt * 8 + 2 * t;
            if (row0 < N)
                *(__half2*)(g_WhH + (size_t)row0 * OC_ + col) =
                    __floats2half2_rn(c[mt][nt][0], c[mt][nt][1]);
            int row1 = row0 + 8;
            if (row1 < N)
                *(__half2*)(g_WhH + (size_t)row1 * OC_ + col) =
                    __floats2half2_rn(c[mt][nt][2], c[mt][nt][3]);
        }
    }

    // ---- fused scores from register fragments (fp32) ----
    float ds[2][2][2] = {}, dd[2][2][2] = {};
    #pragma unroll
    for (int nt = 0; nt < 8; nt++) {
        int col0 = wn + nt * 8 + 2 * t;
        int hgl = col0 >> 5;
        int j = col0 & 31;
        float as0 = sA[hgl * 64 + j],      as1 = sA[hgl * 64 + j + 1];
        float ad0 = sA[hgl * 64 + 32 + j], ad1 = sA[hgl * 64 + 33 + j];
        int hh = nt >> 2;
        #pragma unroll
        for (int mt = 0; mt < 2; mt++) {
            ds[mt][0][hh] += c[mt][nt][0] * as0 + c[mt][nt][1] * as1;
            ds[mt][1][hh] += c[mt][nt][2] * as0 + c[mt][nt][3] * as1;
            dd[mt][0][hh] += c[mt][nt][0] * ad0 + c[mt][nt][1] * ad1;
            dd[mt][1][hh] += c[mt][nt][2] * ad0 + c[mt][nt][3] * ad1;
        }
    }
    int hbase = wn >> 5;
    #pragma unroll
    for (int mt = 0; mt < 2; mt++)
        #pragma unroll
        for (int rh = 0; rh < 2; rh++)
            #pragma unroll
            for (int hh = 0; hh < 2; hh++) {
                float vs = ds[mt][rh][hh];
                float vd = dd[mt][rh][hh];
                vs += __shfl_xor_sync(0xFFFFFFFFu, vs, 1);
                vs += __shfl_xor_sync(0xFFFFFFFFu, vs, 2);
                vd += __shfl_xor_sync(0xFFFFFFFFu, vd, 1);
                vd += __shfl_xor_sync(0xFFFFFFFFu, vd, 2);
                if (t == 0) {
                    int row = br + wm + mt * 16 + g + rh * 8;
                    if (row < N) {
                        g_ssrc[row * HEADS_ + hbase + hh] = vs;
                        g_sdst[row * HEADS_ + hbase + hh] = vd;
                    }
                }
            }
}

// ---------------- pull segment-max + leaky + exp + global sum --------------
__global__ __launch_bounds__(256) void nodemax_kernel(int N) {
    __shared__ float ssum[8][4];
    int gw   = (blockIdx.x * blockDim.x + threadIdx.x) >> 5;
    int lane = threadIdx.x & 31;
    int wrp  = threadIdx.x >> 5;
    bool valid = gw < N;

    float ni = neg_inf();
    float e0 = 0.f, e1 = 0.f, e2 = 0.f, e3 = 0.f;
    if (valid) {
        int start = g_rowptr[gw];
        int cnt   = g_deg[gw];
        float m0 = ni, m1 = ni, m2 = ni, m3 = ni;
        for (int i = lane; i < cnt; i += 32) {
            int s = g_esrc[start + i];
            float4 v = *(const float4*)(g_ssrc + (size_t)s * HEADS_);
            m0 = fmaxf(m0, v.x); m1 = fmaxf(m1, v.y);
            m2 = fmaxf(m2, v.z); m3 = fmaxf(m3, v.w);
        }
        #pragma unroll
        for (int o = 16; o >= 1; o >>= 1) {
            m0 = fmaxf(m0, __shfl_xor_sync(0xFFFFFFFFu, m0, o));
            m1 = fmaxf(m1, __shfl_xor_sync(0xFFFFFFFFu, m1, o));
            m2 = fmaxf(m2, __shfl_xor_sync(0xFFFFFFFFu, m2, o));
            m3 = fmaxf(m3, __shfl_xor_sync(0xFFFFFFFFu, m3, o));
        }
        if (lane == 0) {
            float4 sd = *(const float4*)(g_sdst + (size_t)gw * HEADS_);
            float v0 = m0 + sd.x; v0 = v0 > 0.f ? v0 : NEG_SLOPE_ * v0;
            float v1 = m1 + sd.y; v1 = v1 > 0.f ? v1 : NEG_SLOPE_ * v1;
            float v2 = m2 + sd.z; v2 = v2 > 0.f ? v2 : NEG_SLOPE_ * v2;
            float v3 = m3 + sd.w; v3 = v3 > 0.f ? v3 : NEG_SLOPE_ * v3;
            e0 = __expf(v0); e1 = __expf(v1);
            e2 = __expf(v2); e3 = __expf(v3);
            *(float4*)(g_attn + (size_t)gw * HEADS_) = make_float4(e0, e1, e2, e3);
        }
    }
    if (lane == 0) {
        ssum[wrp][0] = e0; ssum[wrp][1] = e1;
        ssum[wrp][2] = e2; ssum[wrp][3] = e3;
    }
    __syncthreads();
    if (threadIdx.x < 4) {
        float s = ssum[0][threadIdx.x];
        #pragma unroll
        for (int w = 1; w < 8; w++) s += ssum[w][threadIdx.x];
        atomicAdd(&g_gsum[threadIdx.x], s);
    }
}

// ---------------- pull aggregation (fp16 gather, fp32 accumulate) ----------
__global__ __launch_bounds__(256) void aggregate_kernel(float* __restrict__ out, int N) {
    int gw   = (blockIdx.x * blockDim.x + threadIdx.x) >> 5;
    int lane = threadIdx.x & 31;
    if (gw >= N) return;
    int start = g_rowptr[gw];
    int end   = start + g_deg[gw];

    float ax = 0.f, ay = 0.f, az = 0.f, aw = 0.f;
    const __half* whl = g_WhH + lane * 4;   // lane covers cols [lane*4, lane*4+4)
    int i = start;
    for (; i + 7 < end; i += 8) {
        uint2 u0 = *(const uint2*)(whl + (size_t)g_esrc[i + 0] * OC_);
        uint2 u1 = *(const uint2*)(whl + (size_t)g_esrc[i + 1] * OC_);
        uint2 u2 = *(const uint2*)(whl + (size_t)g_esrc[i + 2] * OC_);
        uint2 u3 = *(const uint2*)(whl + (size_t)g_esrc[i + 3] * OC_);
        uint2 u4 = *(const uint2*)(whl + (size_t)g_esrc[i + 4] * OC_);
        uint2 u5 = *(const uint2*)(whl + (size_t)g_esrc[i + 5] * OC_);
        uint2 u6 = *(const uint2*)(whl + (size_t)g_esrc[i + 6] * OC_);
        uint2 u7 = *(const uint2*)(whl + (size_t)g_esrc[i + 7] * OC_);
        float2 a0 = __half22float2(*(__half2*)&u0.x), b0 = __half22float2(*(__half2*)&u0.y);
        float2 a1 = __half22float2(*(__half2*)&u1.x), b1 = __half22float2(*(__half2*)&u1.y);
        float2 a2 = __half22float2(*(__half2*)&u2.x), b2 = __half22float2(*(__half2*)&u2.y);
        float2 a3 = __half22float2(*(__half2*)&u3.x), b3 = __half22float2(*(__half2*)&u3.y);
        float2 a4 = __half22float2(*(__half2*)&u4.x), b4 = __half22float2(*(__half2*)&u4.y);
        float2 a5 = __half22float2(*(__half2*)&u5.x), b5 = __half22float2(*(__half2*)&u5.y);
        float2 a6 = __half22float2(*(__half2*)&u6.x), b6 = __half22float2(*(__half2*)&u6.y);
        float2 a7 = __half22float2(*(__half2*)&u7.x), b7 = __half22float2(*(__half2*)&u7.y);
        ax += (a0.x + a1.x) + (a2.x + a3.x) + ((a4.x + a5.x) + (a6.x + a7.x));
        ay += (a0.y + a1.y) + (a2.y + a3.y) + ((a4.y + a5.y) + (a6.y + a7.y));
        az += (b0.x + b1.x) + (b2.x + b3.x) + ((b4.x + b5.x) + (b6.x + b7.x));
        aw += (b0.y + b1.y) + (b2.y + b3.y) + ((b4.y + b5.y) + (b6.y + b7.y));
    }
    for (; i < end; i++) {
        uint2 u = *(const uint2*)(whl + (size_t)g_esrc[i] * OC_);
        float2 a = __half22float2(*(__half2*)&u.x), b = __half22float2(*(__half2*)&u.y);
        ax += a.x; ay += a.y; az += b.x; aw += b.y;
    }

    int head = lane >> 3;
    float attn = g_attn[(size_t)gw * HEADS_ + head] / g_gsum[head];
    *(float4*)(out + (size_t)gw * OC_ + lane * 4) =
        make_float4(ax * attn, ay * attn, az * attn, aw * attn);
}

// ---------------- launch: gemm kept at submission index 3 for ncu ----------
extern "C" void kernel_launch(void* const* d_in, const int* in_sizes, int n_in,
                              void* d_out, int out_size) {
    const float* h  = (const float*)d_in[0];
    const int*   ei = (const int*)d_in[1];
    const float* W  = (const float*)d_in[2];
    const float* a  = (const float*)d_in[3];
    float* out = (float*)d_out;

    int N = in_sizes[0] / INF_;
    int E = in_sizes[1] / 2;
    int nb = (N + 1023) / 1024;

    static cudaStream_t s2 = nullptr;
    static cudaEvent_t e0 = nullptr, e2 = nullptr;
    if (s2 == nullptr) {
        cudaStreamCreateWithFlags(&s2, cudaStreamNonBlocking);
        cudaEventCreateWithFlags(&e0, cudaEventDisableTiming);
        cudaEventCreateWithFlags(&e2, cudaEventDisableTiming);
    }

    // fork: CSR build chain on s2; W conversion + GEMM on the main stream
    cudaEventRecord(e0, 0);
    cudaStreamWaitEvent(s2, e0, 0);

    // submission 0: W hi/lo pre-conversion (main stream, before gemm)
    wconv_kernel<<<64, 256>>>(W);
    // submissions 1-2 (CSR head on s2)
    init_kernel<<<(N + 255) / 256, 256, 0, s2>>>(N);
    count_kernel<<<((E + 3) / 4 + 255) / 256, 256, 0, s2>>>(ei, E);
    // submission 3: gemm (ncu capture target)
    gemm_kernel<<<(N + 127) / 128, 256>>>(h, a, N);
    // CSR tail on s2 (in-stream order preserved)
    scan1_kernel<<<nb, 1024, 0, s2>>>(N);
    scan2_kernel<<<1, 128, 0, s2>>>(nb);
    scan3_kernel<<<(N + 255) / 256, 256, 0, s2>>>(N);
    scatter_kernel<<<(E + 255) / 256, 256, 0, s2>>>(ei, E);
    cudaEventRecord(e2, s2);

    // join: nodemax needs CSR + scores
    cudaStreamWaitEvent(0, e2, 0);

    nodemax_kernel<<<(N * 32 + 255) / 256, 256>>>(N);
    aggregate_kernel<<<(N * 32 + 255) / 256, 256>>>(out, N);
}

// round 13
// speedup vs baseline: 1.2526x; 1.0128x over previous
#include <cuda_runtime.h>
#include <cuda_fp16.h>
#include <cuda_bf16.h>
#include <cstdint>

#define NMAX   100096
#define EMAX   1600000
#define INF_   128
#define OC_    128
#define HEADS_ 4
#define OUTF_  32
#define NEG_SLOPE_ 0.2f

// ---------------- scratch ----------------
__device__ __half g_WhH[(size_t)NMAX * OC_];    // 25.6 MB (L2-resident)
__device__ __nv_bfloat16 g_WbH[128 * 128];      // W hi, [n][k] bf16
__device__ __nv_bfloat16 g_WbL[128 * 128];      // W lo, [n][k] bf16
__device__ float g_ssrc[(size_t)NMAX * HEADS_];
__device__ float g_sdst[(size_t)NMAX * HEADS_];
__device__ float g_attn[(size_t)NMAX * HEADS_]; // unnormalized exp(nscore)
__device__ float g_gsum[HEADS_];
__device__ int   g_deg[NMAX];
__device__ int   g_incl[NMAX];
__device__ int   g_rowptr[NMAX];
__device__ int   g_cursor[NMAX];
__device__ int   g_esrc[EMAX];
__device__ int   g_bsum[128];
__device__ int   g_boff[128];

__device__ __forceinline__ float neg_inf() { return __int_as_float(0xFF800000); }

__device__ __forceinline__ uint32_t pack_bf2(float x, float y) {
    __nv_bfloat162 p = __floats2bfloat162_rn(x, y);   // .x = low half
    return *reinterpret_cast<uint32_t*>(&p);
}

__device__ __forceinline__ void mma_bf16(float* c, const uint32_t* a, const uint32_t* b) {
    asm volatile(
        "mma.sync.aligned.m16n8k16.row.col.f32.bf16.bf16.f32 "
        "{%0,%1,%2,%3},{%4,%5,%6,%7},{%8,%9},{%0,%1,%2,%3};"
        : "+f"(c[0]), "+f"(c[1]), "+f"(c[2]), "+f"(c[3])
        : "r"(a[0]), "r"(a[1]), "r"(a[2]), "r"(a[3]), "r"(b[0]), "r"(b[1]));
}

// ---------------- init: zero deg, reset global sums ------------------------
__global__ void init_kernel(int N) {
    int i = blockIdx.x * blockDim.x + threadIdx.x;
    if (i < N) g_deg[i] = 0;
    if (i == 0) {
        #pragma unroll
        for (int h = 0; h < HEADS_; h++) g_gsum[h] = 0.f;
    }
}

// ---------------- W pre-conversion: fp32 [k][n] -> bf16 hi/lo [n][k] -------
__global__ void wconv_kernel(const float* __restrict__ W) {
    int idx = blockIdx.x * blockDim.x + threadIdx.x;
    if (idx >= 128 * 128) return;
    int k = idx >> 7, n = idx & 127;
    float v = W[idx];
    __nv_bfloat16 hi = __float2bfloat16(v);
    float rem = v - __bfloat162float(hi);
    g_WbH[n * 128 + k] = hi;
    g_WbL[n * 128 + k] = __float2bfloat16(rem);
}

// ---------------- degree histogram (4 edges per thread) --------------------
__global__ void count_kernel(const int* __restrict__ ei, int E) {
    int t = blockIdx.x * blockDim.x + threadIdx.x;
    int base = t * 4;
    if (base + 3 < E) {
        int4 d = *(const int4*)(ei + E + base);
        atomicAdd(&g_deg[d.x], 1); atomicAdd(&g_deg[d.y], 1);
        atomicAdd(&g_deg[d.z], 1); atomicAdd(&g_deg[d.w], 1);
    } else {
        for (int e = base; e < E; e++) atomicAdd(&g_deg[ei[E + e]], 1);
    }
}

// ---------------- 3-phase exclusive scan of degrees ------------------------
__global__ void scan1_kernel(int N) {
    __shared__ int s[1024];
    int tid = threadIdx.x;
    int i = blockIdx.x * 1024 + tid;
    s[tid] = (i < N) ? g_deg[i] : 0;
    __syncthreads();
    for (int o = 1; o < 1024; o <<= 1) {
        int t = (tid >= o) ? s[tid - o] : 0;
        __syncthreads();
        s[tid] += t;
        __syncthreads();
    }
    if (i < N) g_incl[i] = s[tid];
    if (tid == 1023) g_bsum[blockIdx.x] = s[1023];
}

// parallel scan of up to 128 block sums
__global__ void scan2_kernel(int nb) {
    __shared__ int wsum[4], woff[4];
    int tid = threadIdx.x;
    int lane = tid & 31, w = tid >> 5;
    int v = (tid < nb) ? g_bsum[tid] : 0;
    int x = v;
    #pragma unroll
    for (int o = 1; o < 32; o <<= 1) {
        int y = __shfl_up_sync(0xFFFFFFFFu, x, o);
        if (lane >= o) x += y;
    }
    if (lane == 31) wsum[w] = x;
    __syncthreads();
    if (tid == 0) {
        int acc = 0;
        #pragma unroll
        for (int i = 0; i < 4; i++) { woff[i] = acc; acc += wsum[i]; }
    }
    __syncthreads();
    if (tid < nb) g_boff[tid] = x - v + woff[w];
}

__global__ void scan3_kernel(int N) {
    int i = blockIdx.x * blockDim.x + threadIdx.x;
    if (i >= N) return;
    int start = g_incl[i] - g_deg[i] + g_boff[i >> 10];
    g_rowptr[i] = start;
    g_cursor[i] = start;
}

// ---------------- scatter src ids into CSR order ---------------------------
__global__ void scatter_kernel(const int* __restrict__ ei, int E) {
    int e = blockIdx.x * blockDim.x + threadIdx.x;
    if (e >= E) return;
    int src = ei[e];
    int dst = ei[E + e];
    int pos = atomicAdd(&g_cursor[dst], 1);
    g_esrc[pos] = src;
}

// ---------------- 3x bf16 m16n8k16 GEMM, double-buffered K loop ------------
// smem rows use 12-word stride: (m*12 + t) mod 32 is conflict-free for the
// fragment-load pattern (8 consecutive rows x t in 0..3).
__global__ __launch_bounds__(256, 2) void gemm_kernel(
    const float* __restrict__ A, const float* __restrict__ av_g, int N)
{
    __shared__ uint32_t AsH[2][128 * 12];
    __shared__ uint32_t AsL[2][128 * 12];
    __shared__ uint32_t BsH[2][128 * 12];
    __shared__ uint32_t BsL[2][128 * 12];
    __shared__ float sA[256];       // attention vector a: [head][src32|dst32]

    int tid = threadIdx.x;
    int lane = tid & 31, wid = tid >> 5;
    int g = lane >> 2, t = lane & 3;
    int wm = (wid & 3) * 32;
    int wn = (wid >> 2) * 64;
    int br = blockIdx.x * 128;

    sA[tid] = av_g[tid];

    int arow = tid >> 1;            // 0..127
    int ak   = (tid & 1) * 8;       // k offset within 16-tile: 0 or 8
    int bn_  = tid >> 1;            // B n row
    int bkof = (tid & 1) * 8;
    int grow = br + arow;
    bool arok = grow < N;

    float c[2][8][4];
    #pragma unroll
    for (int mt = 0; mt < 2; mt++)
        #pragma unroll
        for (int nt = 0; nt < 8; nt++)
            #pragma unroll
            for (int q = 0; q < 4; q++) c[mt][nt][q] = 0.f;

    // ---- helper lambdas -------------------------------------------------
    auto load_a = [&](int k0, float* av) {
        av[0]=av[1]=av[2]=av[3]=av[4]=av[5]=av[6]=av[7]=0.f;
        if (arok) {
            float4 a0 = *(const float4*)(A + (size_t)grow * INF_ + k0 + ak);
            float4 a1 = *(const float4*)(A + (size_t)grow * INF_ + k0 + ak + 4);
            av[0] = a0.x; av[1] = a0.y; av[2] = a0.z; av[3] = a0.w;
            av[4] = a1.x; av[5] = a1.y; av[6] = a1.z; av[7] = a1.w;
        }
    };
    auto store_tile = [&](int buf, const float* av, uint4 wbh, uint4 wbl) {
        uint32_t hw[4], lw[4];
        #pragma unroll
        for (int j = 0; j < 4; j++) {
            float x = av[2 * j], y = av[2 * j + 1];
            __nv_bfloat16 xh = __float2bfloat16(x);
            __nv_bfloat16 yh = __float2bfloat16(y);
            float xr = x - __bfloat162float(xh);
            float yr = y - __bfloat162float(yh);
            __nv_bfloat162 ph; ph.x = xh; ph.y = yh;
            hw[j] = *reinterpret_cast<uint32_t*>(&ph);
            lw[j] = pack_bf2(xr, yr);
        }
        *(uint4*)&AsH[buf][arow * 12 + (ak >> 1)] = make_uint4(hw[0], hw[1], hw[2], hw[3]);
        *(uint4*)&AsL[buf][arow * 12 + (ak >> 1)] = make_uint4(lw[0], lw[1], lw[2], lw[3]);
        *(uint4*)&BsH[buf][bn_ * 12 + (bkof >> 1)] = wbh;
        *(uint4*)&BsL[buf][bn_ * 12 + (bkof >> 1)] = wbl;
    };

    // ---- prologue: tile 0 ----
    {
        float av[8];
        load_a(0, av);
        uint4 wbh = *(const uint4*)(g_WbH + (size_t)bn_ * 128 + bkof);
        uint4 wbl = *(const uint4*)(g_WbL + (size_t)bn_ * 128 + bkof);
        store_tile(0, av, wbh, wbl);
    }
    __syncthreads();

    // ---- main loop: 8 K-tiles, double-buffered ----
    #pragma unroll
    for (int kt = 0; kt < 8; kt++) {
        int cur = kt & 1;
        // prefetch next tile's global data (overlaps with MMAs below)
        float av2[8];
        uint4 nbh, nbl;
        if (kt < 7) {
            int k0 = (kt + 1) * 16;
            load_a(k0, av2);
            nbh = *(const uint4*)(g_WbH + (size_t)bn_ * 128 + k0 + bkof);
            nbl = *(const uint4*)(g_WbL + (size_t)bn_ * 128 + k0 + bkof);
        }

        // fragments + MMAs from current buffer
        uint32_t afh[2][4], afl[2][4];
        #pragma unroll
        for (int mt = 0; mt < 2; mt++) {
            int m0 = (wm + mt * 16 + g) * 12;
            int m1 = (wm + mt * 16 + g + 8) * 12;
            afh[mt][0] = AsH[cur][m0 + t];     afh[mt][1] = AsH[cur][m1 + t];
            afh[mt][2] = AsH[cur][m0 + t + 4]; afh[mt][3] = AsH[cur][m1 + t + 4];
            afl[mt][0] = AsL[cur][m0 + t];     afl[mt][1] = AsL[cur][m1 + t];
            afl[mt][2] = AsL[cur][m0 + t + 4]; afl[mt][3] = AsL[cur][m1 + t + 4];
        }
        #pragma unroll
        for (int nt = 0; nt < 8; nt++) {
            int nb = (wn + nt * 8 + g) * 12;
            uint32_t bfh[2], bfl[2];
            bfh[0] = BsH[cur][nb + t]; bfh[1] = BsH[cur][nb + t + 4];
            bfl[0] = BsL[cur][nb + t]; bfl[1] = BsL[cur][nb + t + 4];
            #pragma unroll
            for (int mt = 0; mt < 2; mt++) {
                mma_bf16(c[mt][nt], afl[mt], bfh);   // lo*hi
                mma_bf16(c[mt][nt], afh[mt], bfl);   // hi*lo
                mma_bf16(c[mt][nt], afh[mt], bfh);   // hi*hi
            }
        }

        // convert + store next tile, then one sync
        if (kt < 7) {
            store_tile(cur ^ 1, av2, nbh, nbl);
            __syncthreads();
        }
    }

    // ---- store Wh as fp16 (only consumer is the aggregate gather) ----
    #pragma unroll
    for (int mt = 0; mt < 2; mt++) {
        #pragma unroll
        for (int nt = 0; nt < 8; nt++) {
            int row0 = br + wm + mt * 16 + g;
            int col = wn + nt * 8 + 2 * t;
            if (row0 < N)
                *(__half2*)(g_WhH + (size_t)row0 * OC_ + col) =
                    __floats2half2_rn(c[mt][nt][0], c[mt][nt][1]);
            int row1 = row0 + 8;
            if (row1 < N)
                *(__half2*)(g_WhH + (size_t)row1 * OC_ + col) =
                    __floats2half2_rn(c[mt][nt][2], c[mt][nt][3]);
        }
    }

    // ---- fused scores from register fragments (fp32) ----
    float ds[2][2][2] = {}, dd[2][2][2] = {};
    #pragma unroll
    for (int nt = 0; nt < 8; nt++) {
        int col0 = wn + nt * 8 + 2 * t;
        int hgl = col0 >> 5;
        int j = col0 & 31;
        float as0 = sA[hgl * 64 + j],      as1 = sA[hgl * 64 + j + 1];
        float ad0 = sA[hgl * 64 + 32 + j], ad1 = sA[hgl * 64 + 33 + j];
        int hh = nt >> 2;
        #pragma unroll
        for (int mt = 0; mt < 2; mt++) {
            ds[mt][0][hh] += c[mt][nt][0] * as0 + c[mt][nt][1] * as1;
            ds[mt][1][hh] += c[mt][nt][2] * as0 + c[mt][nt][3] * as1;
            dd[mt][0][hh] += c[mt][nt][0] * ad0 + c[mt][nt][1] * ad1;
            dd[mt][1][hh] += c[mt][nt][2] * ad0 + c[mt][nt][3] * ad1;
        }
    }
    int hbase = wn >> 5;
    #pragma unroll
    for (int mt = 0; mt < 2; mt++)
        #pragma unroll
        for (int rh = 0; rh < 2; rh++)
            #pragma unroll
            for (int hh = 0; hh < 2; hh++) {
                float vs = ds[mt][rh][hh];
                float vd = dd[mt][rh][hh];
                vs += __shfl_xor_sync(0xFFFFFFFFu, vs, 1);
                vs += __shfl_xor_sync(0xFFFFFFFFu, vs, 2);
                vd += __shfl_xor_sync(0xFFFFFFFFu, vd, 1);
                vd += __shfl_xor_sync(0xFFFFFFFFu, vd, 2);
                if (t == 0) {
                    int row = br + wm + mt * 16 + g + rh * 8;
                    if (row < N) {
                        g_ssrc[row * HEADS_ + hbase + hh] = vs;
                        g_sdst[row * HEADS_ + hbase + hh] = vd;
                    }
                }
            }
}

// ---------------- pull segment-max + leaky + exp + global sum --------------
__global__ __launch_bounds__(256) void nodemax_kernel(int N) {
    __shared__ float ssum[8][4];
    int gw   = (blockIdx.x * blockDim.x + threadIdx.x) >> 5;
    int lane = threadIdx.x & 31;
    int wrp  = threadIdx.x >> 5;
    bool valid = gw < N;

    float ni = neg_inf();
    float e0 = 0.f, e1 = 0.f, e2 = 0.f, e3 = 0.f;
    if (valid) {
        int start = g_rowptr[gw];
        int cnt   = g_deg[gw];
        float m0 = ni, m1 = ni, m2 = ni, m3 = ni;
        for (int i = lane; i < cnt; i += 32) {
            int s = g_esrc[start + i];
            float4 v = *(const float4*)(g_ssrc + (size_t)s * HEADS_);
            m0 = fmaxf(m0, v.x); m1 = fmaxf(m1, v.y);
            m2 = fmaxf(m2, v.z); m3 = fmaxf(m3, v.w);
        }
        #pragma unroll
        for (int o = 16; o >= 1; o >>= 1) {
            m0 = fmaxf(m0, __shfl_xor_sync(0xFFFFFFFFu, m0, o));
            m1 = fmaxf(m1, __shfl_xor_sync(0xFFFFFFFFu, m1, o));
            m2 = fmaxf(m2, __shfl_xor_sync(0xFFFFFFFFu, m2, o));
            m3 = fmaxf(m3, __shfl_xor_sync(0xFFFFFFFFu, m3, o));
        }
        if (lane == 0) {
            float4 sd = *(const float4*)(g_sdst + (size_t)gw * HEADS_);
            float v0 = m0 + sd.x; v0 = v0 > 0.f ? v0 : NEG_SLOPE_ * v0;
            float v1 = m1 + sd.y; v1 = v1 > 0.f ? v1 : NEG_SLOPE_ * v1;
            float v2 = m2 + sd.z; v2 = v2 > 0.f ? v2 : NEG_SLOPE_ * v2;
            float v3 = m3 + sd.w; v3 = v3 > 0.f ? v3 : NEG_SLOPE_ * v3;
            e0 = __expf(v0); e1 = __expf(v1);
            e2 = __expf(v2); e3 = __expf(v3);
            *(float4*)(g_attn + (size_t)gw * HEADS_) = make_float4(e0, e1, e2, e3);
        }
    }
    if (lane == 0) {
        ssum[wrp][0] = e0; ssum[wrp][1] = e1;
        ssum[wrp][2] = e2; ssum[wrp][3] = e3;
    }
    __syncthreads();
    if (threadIdx.x < 4) {
        float s = ssum[0][threadIdx.x];
        #pragma unroll
        for (int w = 1; w < 8; w++) s += ssum[w][threadIdx.x];
        atomicAdd(&g_gsum[threadIdx.x], s);
    }
}

// ---------------- pull aggregation (fp16 gather, fp32 accumulate) ----------
__global__ __launch_bounds__(256) void aggregate_kernel(float* __restrict__ out, int N) {
    int gw   = (blockIdx.x * blockDim.x + threadIdx.x) >> 5;
    int lane = threadIdx.x & 31;
    if (gw >= N) return;
    int start = g_rowptr[gw];
    int end   = start + g_deg[gw];

    float ax = 0.f, ay = 0.f, az = 0.f, aw = 0.f;
    const __half* whl = g_WhH + lane * 4;   // lane covers cols [lane*4, lane*4+4)
    int i = start;
    for (; i + 7 < end; i += 8) {
        uint2 u0 = *(const uint2*)(whl + (size_t)g_esrc[i + 0] * OC_);
        uint2 u1 = *(const uint2*)(whl + (size_t)g_esrc[i + 1] * OC_);
        uint2 u2 = *(const uint2*)(whl + (size_t)g_esrc[i + 2] * OC_);
        uint2 u3 = *(const uint2*)(whl + (size_t)g_esrc[i + 3] * OC_);
        uint2 u4 = *(const uint2*)(whl + (size_t)g_esrc[i + 4] * OC_);
        uint2 u5 = *(const uint2*)(whl + (size_t)g_esrc[i + 5] * OC_);
        uint2 u6 = *(const uint2*)(whl + (size_t)g_esrc[i + 6] * OC_);
        uint2 u7 = *(const uint2*)(whl + (size_t)g_esrc[i + 7] * OC_);
        float2 a0 = __half22float2(*(__half2*)&u0.x), b0 = __half22float2(*(__half2*)&u0.y);
        float2 a1 = __half22float2(*(__half2*)&u1.x), b1 = __half22float2(*(__half2*)&u1.y);
        float2 a2 = __half22float2(*(__half2*)&u2.x), b2 = __half22float2(*(__half2*)&u2.y);
        float2 a3 = __half22float2(*(__half2*)&u3.x), b3 = __half22float2(*(__half2*)&u3.y);
        float2 a4 = __half22float2(*(__half2*)&u4.x), b4 = __half22float2(*(__half2*)&u4.y);
        float2 a5 = __half22float2(*(__half2*)&u5.x), b5 = __half22float2(*(__half2*)&u5.y);
        float2 a6 = __half22float2(*(__half2*)&u6.x), b6 = __half22float2(*(__half2*)&u6.y);
        float2 a7 = __half22float2(*(__half2*)&u7.x), b7 = __half22float2(*(__half2*)&u7.y);
        ax += (a0.x + a1.x) + (a2.x + a3.x) + ((a4.x + a5.x) + (a6.x + a7.x));
        ay += (a0.y + a1.y) + (a2.y + a3.y) + ((a4.y + a5.y) + (a6.y + a7.y));
        az += (b0.x + b1.x) + (b2.x + b3.x) + ((b4.x + b5.x) + (b6.x + b7.x));
        aw += (b0.y + b1.y) + (b2.y + b3.y) + ((b4.y + b5.y) + (b6.y + b7.y));
    }
    for (; i < end; i++) {
        uint2 u = *(const uint2*)(whl + (size_t)g_esrc[i] * OC_);
        float2 a = __half22float2(*(__half2*)&u.x), b = __half22float2(*(__half2*)&u.y);
        ax += a.x; ay += a.y; az += b.x; aw += b.y;
    }

    int head = lane >> 3;
    float attn = g_attn[(size_t)gw * HEADS_ + head] / g_gsum[head];
    *(float4*)(out + (size_t)gw * OC_ + lane * 4) =
        make_float4(ax * attn, ay * attn, az * attn, aw * attn);
}

// ---------------- launch: gemm kept at submission index 3 for ncu ----------
extern "C" void kernel_launch(void* const* d_in, const int* in_sizes, int n_in,
                              void* d_out, int out_size) {
    const float* h  = (const float*)d_in[0];
    const int*   ei = (const int*)d_in[1];
    const float* W  = (const float*)d_in[2];
    const float* a  = (const float*)d_in[3];
    float* out = (float*)d_out;

    int N = in_sizes[0] / INF_;
    int E = in_sizes[1] / 2;
    int nb = (N + 1023) / 1024;

    static cudaStream_t s2 = nullptr;
    static cudaEvent_t e0 = nullptr, e2 = nullptr;
    if (s2 == nullptr) {
        cudaStreamCreateWithFlags(&s2, cudaStreamNonBlocking);
        cudaEventCreateWithFlags(&e0, cudaEventDisableTiming);
        cudaEventCreateWithFlags(&e2, cudaEventDisableTiming);
    }

    // fork: CSR build chain on s2; W conversion + GEMM on the main stream
    cudaEventRecord(e0, 0);
    cudaStreamWaitEvent(s2, e0, 0);

    // submission 0: W hi/lo pre-conversion (main stream, before gemm)
    wconv_kernel<<<64, 256>>>(W);
    // submissions 1-2 (CSR head on s2)
    init_kernel<<<(N + 255) / 256, 256, 0, s2>>>(N);
    count_kernel<<<((E + 3) / 4 + 255) / 256, 256, 0, s2>>>(ei, E);
    // submission 3: gemm (ncu capture target)
    gemm_kernel<<<(N + 127) / 128, 256>>>(h, a, N);
    // CSR tail on s2 (in-stream order preserved)
    scan1_kernel<<<nb, 1024, 0, s2>>>(N);
    scan2_kernel<<<1, 128, 0, s2>>>(nb);
    scan3_kernel<<<(N + 255) / 256, 256, 0, s2>>>(N);
    scatter_kernel<<<(E + 255) / 256, 256, 0, s2>>>(ei, E);
    cudaEventRecord(e2, s2);

    // join: nodemax needs CSR + scores
    cudaStreamWaitEvent(0, e2, 0);

    nodemax_kernel<<<(N * 32 + 255) / 256, 256>>>(N);
    aggregate_kernel<<<(N * 32 + 255) / 256, 256>>>(out, N);
}

// round 15
// speedup vs baseline: 1.2655x; 1.0103x over previous
#include <cuda_runtime.h>
#include <cuda_fp16.h>
#include <cuda_bf16.h>
#include <cstdint>

#define NMAX   100096
#define EMAX   1600000
#define INF_   128
#define OC_    128
#define HEADS_ 4
#define OUTF_  32
#define NEG_SLOPE_ 0.2f

// ---------------- scratch ----------------
__device__ __half g_WhH[(size_t)NMAX * OC_];    // 25.6 MB (L2-resident)
__device__ __nv_bfloat16 g_WbH[128 * 128];      // W hi, [n][k] bf16
__device__ __nv_bfloat16 g_WbL[128 * 128];      // W lo, [n][k] bf16
__device__ float g_ssrc[(size_t)NMAX * HEADS_];
__device__ float g_sdst[(size_t)NMAX * HEADS_];
__device__ float g_attn[(size_t)NMAX * HEADS_]; // unnormalized exp(nscore)
__device__ float g_gsum[HEADS_];
__device__ int   g_deg[NMAX];
__device__ int   g_rowptr[NMAX];
__device__ int   g_cursor[NMAX];
__device__ int   g_esrc[EMAX];
__device__ int   g_alloc;                        // CSR allocation counter

__device__ __forceinline__ float neg_inf() { return __int_as_float(0xFF800000); }

__device__ __forceinline__ uint32_t pack_bf2(float x, float y) {
    __nv_bfloat162 p = __floats2bfloat162_rn(x, y);   // .x = low half
    return *reinterpret_cast<uint32_t*>(&p);
}

__device__ __forceinline__ void mma_bf16(float* c, const uint32_t* a, const uint32_t* b) {
    asm volatile(
        "mma.sync.aligned.m16n8k16.row.col.f32.bf16.bf16.f32 "
        "{%0,%1,%2,%3},{%4,%5,%6,%7},{%8,%9},{%0,%1,%2,%3};"
        : "+f"(c[0]), "+f"(c[1]), "+f"(c[2]), "+f"(c[3])
        : "r"(a[0]), "r"(a[1]), "r"(a[2]), "r"(a[3]), "r"(b[0]), "r"(b[1]));
}

// ---------------- init: zero deg, reset global sums + alloc ----------------
__global__ void init_kernel(int N) {
    int i = blockIdx.x * blockDim.x + threadIdx.x;
    if (i < N) g_deg[i] = 0;
    if (i == 0) {
        #pragma unroll
        for (int h = 0; h < HEADS_; h++) g_gsum[h] = 0.f;
        g_alloc = 0;
    }
}

// ---------------- W pre-conversion: fp32 [k][n] -> bf16 hi/lo [n][k] -------
__global__ void wconv_kernel(const float* __restrict__ W) {
    int idx = blockIdx.x * blockDim.x + threadIdx.x;
    if (idx >= 128 * 128) return;
    int k = idx >> 7, n = idx & 127;
    float v = W[idx];
    __nv_bfloat16 hi = __float2bfloat16(v);
    float rem = v - __bfloat162float(hi);
    g_WbH[n * 128 + k] = hi;
    g_WbL[n * 128 + k] = __float2bfloat16(rem);
}

// ---------------- degree histogram (4 edges per thread) --------------------
__global__ void count_kernel(const int* __restrict__ ei, int E) {
    int t = blockIdx.x * blockDim.x + threadIdx.x;
    int base = t * 4;
    if (base + 3 < E) {
        int4 d = *(const int4*)(ei + E + base);
        atomicAdd(&g_deg[d.x], 1); atomicAdd(&g_deg[d.y], 1);
        atomicAdd(&g_deg[d.z], 1); atomicAdd(&g_deg[d.w], 1);
    } else {
        for (int e = base; e < E; e++) atomicAdd(&g_deg[ei[E + e]], 1);
    }
}

// ---------------- fused scan: block scan + atomic base allocation ----------
// Rowptr ranges only need to be disjoint; cross-block ordering is irrelevant
// (edge order inside a node's list is already atomic-nondeterministic).
__global__ __launch_bounds__(1024) void scanf_kernel(int N) {
    __shared__ int warp_excl[32];
    __shared__ int s_base;
    int tid = threadIdx.x;
    int lane = tid & 31, w = tid >> 5;
    int i = blockIdx.x * 1024 + tid;
    int d = (i < N) ? g_deg[i] : 0;

    int x = d;
    #pragma unroll
    for (int o = 1; o < 32; o <<= 1) {
        int y = __shfl_up_sync(0xFFFFFFFFu, x, o);
        if (lane >= o) x += y;
    }
    if (lane == 31) warp_excl[w] = x;     // warp totals
    __syncthreads();
    if (w == 0) {
        int v = warp_excl[lane];
        int xx = v;
        #pragma unroll
        for (int o = 1; o < 32; o <<= 1) {
            int y = __shfl_up_sync(0xFFFFFFFFu, xx, o);
            if (lane >= o) xx += y;
        }
        warp_excl[lane] = xx - v;          // exclusive warp offsets
        if (lane == 31) s_base = atomicAdd(&g_alloc, xx);  // block base
    }
    __syncthreads();
    if (i < N) {
        int start = s_base + warp_excl[w] + (x - d);
        g_rowptr[i] = start;
        g_cursor[i] = start;
    }
}

// ---------------- scatter src ids into CSR order ---------------------------
__global__ void scatter_kernel(const int* __restrict__ ei, int E) {
    int e = blockIdx.x * blockDim.x + threadIdx.x;
    if (e >= E) return;
    int src = ei[e];
    int dst = ei[E + e];
    int pos = atomicAdd(&g_cursor[dst], 1);
    g_esrc[pos] = src;
}

// ---------------- 3x bf16 m16n8k16 GEMM, double-buffered, hi/lo interleaved
// smem word layout: row*24 + 2*j + {0=hi,1=lo} for bf16x2 pair j (16 words
// payload, 8 pad). Stride 24 => g*24 mod 32 in {0,24,16,8}: the uint2
// fragment loads tile all 32 banks conflict-free, and all wide accesses are
// 16B/8B aligned (24 = 0 mod 4).
__global__ __launch_bounds__(256, 2) void gemm_kernel(
    const float* __restrict__ A, const float* __restrict__ av_g, int N)
{
    __shared__ __align__(16) uint32_t As2[2][128 * 24];
    __shared__ __align__(16) uint32_t Bs2[2][128 * 24];
    __shared__ float sA[256];       // attention vector a: [head][src32|dst32]

    int tid = threadIdx.x;
    int lane = tid & 31, wid = tid >> 5;
    int g = lane >> 2, t = lane & 3;
    int wm = (wid & 3) * 32;
    int wn = (wid >> 2) * 64;
    int br = blockIdx.x * 128;

    sA[tid] = av_g[tid];

    int arow = tid >> 1;            // 0..127
    int ak   = (tid & 1) * 8;       // k element offset (0/8)
    int akw  = (tid & 1) * 8;       // word offset of this thread's half row
    int bn_  = tid >> 1;            // B n row
    int bkof = (tid & 1) * 8;
    int grow = br + arow;
    bool arok = grow < N;

    float c[2][8][4];
    #pragma unroll
    for (int mt = 0; mt < 2; mt++)
        #pragma unroll
        for (int nt = 0; nt < 8; nt++)
            #pragma unroll
            for (int q = 0; q < 4; q++) c[mt][nt][q] = 0.f;

    auto load_a = [&](int k0, float* av) {
        av[0]=av[1]=av[2]=av[3]=av[4]=av[5]=av[6]=av[7]=0.f;
        if (arok) {
            float4 a0 = *(const float4*)(A + (size_t)grow * INF_ + k0 + ak);
            float4 a1 = *(const float4*)(A + (size_t)grow * INF_ + k0 + ak + 4);
            av[0] = a0.x; av[1] = a0.y; av[2] = a0.z; av[3] = a0.w;
            av[4] = a1.x; av[5] = a1.y; av[6] = a1.z; av[7] = a1.w;
        }
    };
    auto store_tile = [&](int buf, const float* av, uint4 wbh, uint4 wbl) {
        uint32_t hw[4], lw[4];
        #pragma unroll
        for (int j = 0; j < 4; j++) {
            float x = av[2 * j], y = av[2 * j + 1];
            __nv_bfloat16 xh = __float2bfloat16(x);
            __nv_bfloat16 yh = __float2bfloat16(y);
            float xr = x - __bfloat162float(xh);
            float yr = y - __bfloat162float(yh);
            __nv_bfloat162 ph; ph.x = xh; ph.y = yh;
            hw[j] = *reinterpret_cast<uint32_t*>(&ph);
            lw[j] = pack_bf2(xr, yr);
        }
        // interleaved (hi,lo) word pairs; 16B-aligned uint4 stores
        *(uint4*)&As2[buf][arow * 24 + akw]     = make_uint4(hw[0], lw[0], hw[1], lw[1]);
        *(uint4*)&As2[buf][arow * 24 + akw + 4] = make_uint4(hw[2], lw[2], hw[3], lw[3]);
        *(uint4*)&Bs2[buf][bn_ * 24 + akw]      = make_uint4(wbh.x, wbl.x, wbh.y, wbl.y);
        *(uint4*)&Bs2[buf][bn_ * 24 + akw + 4]  = make_uint4(wbh.z, wbl.z, wbh.w, wbl.w);
    };

    // ---- prologue: tile 0 ----
    {
        float av[8];
        load_a(0, av);
        uint4 wbh = *(const uint4*)(g_WbH + (size_t)bn_ * 128 + bkof);
        uint4 wbl = *(const uint4*)(g_WbL + (size_t)bn_ * 128 + bkof);
        store_tile(0, av, wbh, wbl);
    }
    __syncthreads();

    // ---- main loop: 8 K-tiles, double-buffered ----
    #pragma unroll
    for (int kt = 0; kt < 8; kt++) {
        int cur = kt & 1;
        float av2[8];
        uint4 nbh, nbl;
        if (kt < 7) {
            int k0 = (kt + 1) * 16;
            load_a(k0, av2);
            nbh = *(const uint4*)(g_WbH + (size_t)bn_ * 128 + k0 + bkof);
            nbl = *(const uint4*)(g_WbL + (size_t)bn_ * 128 + k0 + bkof);
        }

        // fragments via conflict-free LDS.64 (hi,lo) pairs
        uint32_t afh[2][4], afl[2][4];
        #pragma unroll
        for (int mt = 0; mt < 2; mt++) {
            int m0 = (wm + mt * 16 + g) * 24;
            int m1 = (wm + mt * 16 + g + 8) * 24;
            uint2 p0 = *(uint2*)&As2[cur][m0 + 2 * t];
            uint2 p1 = *(uint2*)&As2[cur][m1 + 2 * t];
            uint2 p2 = *(uint2*)&As2[cur][m0 + 2 * t + 8];
            uint2 p3 = *(uint2*)&As2[cur][m1 + 2 * t + 8];
            afh[mt][0] = p0.x; afl[mt][0] = p0.y;
            afh[mt][1] = p1.x; afl[mt][1] = p1.y;
            afh[mt][2] = p2.x; afl[mt][2] = p2.y;
            afh[mt][3] = p3.x; afl[mt][3] = p3.y;
        }
        #pragma unroll
        for (int nt = 0; nt < 8; nt++) {
            int nb = (wn + nt * 8 + g) * 24;
            uint2 q0 = *(uint2*)&Bs2[cur][nb + 2 * t];
            uint2 q1 = *(uint2*)&Bs2[cur][nb + 2 * t + 8];
            uint32_t bfh[2] = { q0.x, q1.x };
            uint32_t bfl[2] = { q0.y, q1.y };
            #pragma unroll
            for (int mt = 0; mt < 2; mt++) {
                mma_bf16(c[mt][nt], afl[mt], bfh);   // lo*hi
                mma_bf16(c[mt][nt], afh[mt], bfl);   // hi*lo
                mma_bf16(c[mt][nt], afh[mt], bfh);   // hi*hi
            }
        }

        if (kt < 7) {
            store_tile(cur ^ 1, av2, nbh, nbl);
            __syncthreads();
        }
    }

    // ---- store Wh as fp16 (only consumer is the aggregate gather) ----
    #pragma unroll
    for (int mt = 0; mt < 2; mt++) {
        #pragma unroll
        for (int nt = 0; nt < 8; nt++) {
            int row0 = br + wm + mt * 16 + g;
            int col = wn + nt * 8 + 2 * t;
            if (row0 < N)
                *(__half2*)(g_WhH + (size_t)row0 * OC_ + col) =
                    __floats2half2_rn(c[mt][nt][0], c[mt][nt][1]);
            int row1 = row0 + 8;
            if (row1 < N)
                *(__half2*)(g_WhH + (size_t)row1 * OC_ + col) =
                    __floats2half2_rn(c[mt][nt][2], c[mt][nt][3]);
        }
    }

    // ---- fused scores from register fragments (fp32) ----
    float ds[2][2][2] = {}, dd[2][2][2] = {};
    #pragma unroll
    for (int nt = 0; nt < 8; nt++) {
        int col0 = wn + nt * 8 + 2 * t;
        int hgl = col0 >> 5;
        int j = col0 & 31;
        float as0 = sA[hgl * 64 + j],      as1 = sA[hgl * 64 + j + 1];
        float ad0 = sA[hgl * 64 + 32 + j], ad1 = sA[hgl * 64 + 33 + j];
        int hh = nt >> 2;
        #pragma unroll
        for (int mt = 0; mt < 2; mt++) {
            ds[mt][0][hh] += c[mt][nt][0] * as0 + c[mt][nt][1] * as1;
            ds[mt][1][hh] += c[mt][nt][2] * as0 + c[mt][nt][3] * as1;
            dd[mt][0][hh] += c[mt][nt][0] * ad0 + c[mt][nt][1] * ad1;
            dd[mt][1][hh] += c[mt][nt][2] * ad0 + c[mt][nt][3] * ad1;
        }
    }
    int hbase = wn >> 5;
    #pragma unroll
    for (int mt = 0; mt < 2; mt++)
        #pragma unroll
        for (int rh = 0; rh < 2; rh++)
            #pragma unroll
            for (int hh = 0; hh < 2; hh++) {
                float vs = ds[mt][rh][hh];
                float vd = dd[mt][rh][hh];
                vs += __shfl_xor_sync(0xFFFFFFFFu, vs, 1);
                vs += __shfl_xor_sync(0xFFFFFFFFu, vs, 2);
                vd += __shfl_xor_sync(0xFFFFFFFFu, vd, 1);
                vd += __shfl_xor_sync(0xFFFFFFFFu, vd, 2);
                if (t == 0) {
                    int row = br + wm + mt * 16 + g + rh * 8;
                    if (row < N) {
                        g_ssrc[row * HEADS_ + hbase + hh] = vs;
                        g_sdst[row * HEADS_ + hbase + hh] = vd;
                    }
                }
            }
}

// ---------------- pull segment-max + leaky + exp + global sum --------------
__global__ __launch_bounds__(256) void nodemax_kernel(int N) {
    __shared__ float ssum[8][4];
    int gw   = (blockIdx.x * blockDim.x + threadIdx.x) >> 5;
    int lane = threadIdx.x & 31;
    int wrp  = threadIdx.x >> 5;
    bool valid = gw < N;

    float ni = neg_inf();
    float e0 = 0.f, e1 = 0.f, e2 = 0.f, e3 = 0.f;
    if (valid) {
        int start = g_rowptr[gw];
        int cnt   = g_deg[gw];
        float m0 = ni, m1 = ni, m2 = ni, m3 = ni;
        for (int i = lane; i < cnt; i += 32) {
            int s = g_esrc[start + i];
            float4 v = *(const float4*)(g_ssrc + (size_t)s * HEADS_);
            m0 = fmaxf(m0, v.x); m1 = fmaxf(m1, v.y);
            m2 = fmaxf(m2, v.z); m3 = fmaxf(m3, v.w);
        }
        #pragma unroll
        for (int o = 16; o >= 1; o >>= 1) {
            m0 = fmaxf(m0, __shfl_xor_sync(0xFFFFFFFFu, m0, o));
            m1 = fmaxf(m1, __shfl_xor_sync(0xFFFFFFFFu, m1, o));
            m2 = fmaxf(m2, __shfl_xor_sync(0xFFFFFFFFu, m2, o));
            m3 = fmaxf(m3, __shfl_xor_sync(0xFFFFFFFFu, m3, o));
        }
        if (lane == 0) {
            float4 sd = *(const float4*)(g_sdst + (size_t)gw * HEADS_);
            float v0 = m0 + sd.x; v0 = v0 > 0.f ? v0 : NEG_SLOPE_ * v0;
            float v1 = m1 + sd.y; v1 = v1 > 0.f ? v1 : NEG_SLOPE_ * v1;
            float v2 = m2 + sd.z; v2 = v2 > 0.f ? v2 : NEG_SLOPE_ * v2;
            float v3 = m3 + sd.w; v3 = v3 > 0.f ? v3 : NEG_SLOPE_ * v3;
            e0 = __expf(v0); e1 = __expf(v1);
            e2 = __expf(v2); e3 = __expf(v3);
            *(float4*)(g_attn + (size_t)gw * HEADS_) = make_float4(e0, e1, e2, e3);
        }
    }
    if (lane == 0) {
        ssum[wrp][0] = e0; ssum[wrp][1] = e1;
        ssum[wrp][2] = e2; ssum[wrp][3] = e3;
    }
    __syncthreads();
    if (threadIdx.x < 4) {
        float s = ssum[0][threadIdx.x];
        #pragma unroll
        for (int w = 1; w < 8; w++) s += ssum[w][threadIdx.x];
        atomicAdd(&g_gsum[threadIdx.x], s);
    }
}

// ---------------- pull aggregation (fp16 gather, fp32 accumulate) ----------
__global__ __launch_bounds__(256) void aggregate_kernel(float* __restrict__ out, int N) {
    int gw   = (blockIdx.x * blockDim.x + threadIdx.x) >> 5;
    int lane = threadIdx.x & 31;
    if (gw >= N) return;
    int start = g_rowptr[gw];
    int end   = start + g_deg[gw];

    float ax = 0.f, ay = 0.f, az = 0.f, aw = 0.f;
    const __half* whl = g_WhH + lane * 4;   // lane covers cols [lane*4, lane*4+4)
    int i = start;
    for (; i + 7 < end; i += 8) {
        uint2 u0 = *(const uint2*)(whl + (size_t)g_esrc[i + 0] * OC_);
        uint2 u1 = *(const uint2*)(whl + (size_t)g_esrc[i + 1] * OC_);
        uint2 u2 = *(const uint2*)(whl + (size_t)g_esrc[i + 2] * OC_);
        uint2 u3 = *(const uint2*)(whl + (size_t)g_esrc[i + 3] * OC_);
        uint2 u4 = *(const uint2*)(whl + (size_t)g_esrc[i + 4] * OC_);
        uint2 u5 = *(const uint2*)(whl + (size_t)g_esrc[i + 5] * OC_);
        uint2 u6 = *(const uint2*)(whl + (size_t)g_esrc[i + 6] * OC_);
        uint2 u7 = *(const uint2*)(whl + (size_t)g_esrc[i + 7] * OC_);
        float2 a0 = __half22float2(*(__half2*)&u0.x), b0 = __half22float2(*(__half2*)&u0.y);
        float2 a1 = __half22float2(*(__half2*)&u1.x), b1 = __half22float2(*(__half2*)&u1.y);
        float2 a2 = __half22float2(*(__half2*)&u2.x), b2 = __half22float2(*(__half2*)&u2.y);
        float2 a3 = __half22float2(*(__half2*)&u3.x), b3 = __half22float2(*(__half2*)&u3.y);
        float2 a4 = __half22float2(*(__half2*)&u4.x), b4 = __half22float2(*(__half2*)&u4.y);
        float2 a5 = __half22float2(*(__half2*)&u5.x), b5 = __half22float2(*(__half2*)&u5.y);
        float2 a6 = __half22float2(*(__half2*)&u6.x), b6 = __half22float2(*(__half2*)&u6.y);
        float2 a7 = __half22float2(*(__half2*)&u7.x), b7 = __half22float2(*(__half2*)&u7.y);
        ax += (a0.x + a1.x) + (a2.x + a3.x) + ((a4.x + a5.x) + (a6.x + a7.x));
        ay += (a0.y + a1.y) + (a2.y + a3.y) + ((a4.y + a5.y) + (a6.y + a7.y));
        az += (b0.x + b1.x) + (b2.x + b3.x) + ((b4.x + b5.x) + (b6.x + b7.x));
        aw += (b0.y + b1.y) + (b2.y + b3.y) + ((b4.y + b5.y) + (b6.y + b7.y));
    }
    for (; i < end; i++) {
        uint2 u = *(const uint2*)(whl + (size_t)g_esrc[i] * OC_);
        float2 a = __half22float2(*(__half2*)&u.x), b = __half22float2(*(__half2*)&u.y);
        ax += a.x; ay += a.y; az += b.x; aw += b.y;
    }

    int head = lane >> 3;
    float attn = g_attn[(size_t)gw * HEADS_ + head] / g_gsum[head];
    *(float4*)(out + (size_t)gw * OC_ + lane * 4) =
        make_float4(ax * attn, ay * attn, az * attn, aw * attn);
}

// ---------------- launch: gemm kept at submission index 3 for ncu ----------
extern "C" void kernel_launch(void* const* d_in, const int* in_sizes, int n_in,
                              void* d_out, int out_size) {
    const float* h  = (const float*)d_in[0];
    const int*   ei = (const int*)d_in[1];
    const float* W  = (const float*)d_in[2];
    const float* a  = (const float*)d_in[3];
    float* out = (float*)d_out;

    int N = in_sizes[0] / INF_;
    int E = in_sizes[1] / 2;
    int nb = (N + 1023) / 1024;

    static cudaStream_t s2 = nullptr;
    static cudaEvent_t e0 = nullptr, e2 = nullptr;
    if (s2 == nullptr) {
        cudaStreamCreateWithFlags(&s2, cudaStreamNonBlocking);
        cudaEventCreateWithFlags(&e0, cudaEventDisableTiming);
        cudaEventCreateWithFlags(&e2, cudaEventDisableTiming);
    }

    // fork: CSR build chain on s2; W conversion + GEMM on the main stream
    cudaEventRecord(e0, 0);
    cudaStreamWaitEvent(s2, e0, 0);

    // submission 0: W hi/lo pre-conversion (main stream, before gemm)
    wconv_kernel<<<64, 256>>>(W);
    // submissions 1-2 (CSR head on s2)
    init_kernel<<<(N + 255) / 256, 256, 0, s2>>>(N);
    count_kernel<<<((E + 3) / 4 + 255) / 256, 256, 0, s2>>>(ei, E);
    // submission 3: gemm (ncu capture target)
    gemm_kernel<<<(N + 127) / 128, 256>>>(h, a, N);
    // CSR tail on s2 (fused scan + scatter)
    scanf_kernel<<<nb, 1024, 0, s2>>>(N);
    scatter_kernel<<<(E + 255) / 256, 256, 0, s2>>>(ei, E);
    cudaEventRecord(e2, s2);

    // join: nodemax needs CSR + scores
    cudaStreamWaitEvent(0, e2, 0);

    nodemax_kernel<<<(N * 32 + 255) / 256, 256>>>(N);
    aggregate_kernel<<<(N * 32 + 255) / 256, 256>>>(out, N);
}

// round 17
// speedup vs baseline: 1.2751x; 1.0076x over previous
#include <cuda_runtime.h>
#include <cuda_fp16.h>
#include <cuda_bf16.h>
#include <cstdint>

#define NMAX   100096
#define EMAX   1600000
#define INF_   128
#define OC_    128
#define HEADS_ 4
#define OUTF_  32
#define NEG_SLOPE_ 0.2f

// ---------------- scratch ----------------
__device__ __half g_WhH[(size_t)NMAX * OC_];    // 25.6 MB (L2-resident)
__device__ __nv_bfloat16 g_WbH[128 * 128];      // W hi, [n][k] bf16
__device__ __nv_bfloat16 g_WbL[128 * 128];      // W lo, [n][k] bf16
__device__ float g_ssrc[(size_t)NMAX * HEADS_];
__device__ float g_sdst[(size_t)NMAX * HEADS_];
__device__ float g_attn[(size_t)NMAX * HEADS_]; // unnormalized exp(nscore)
__device__ float g_gsum[HEADS_];
__device__ int   g_deg[NMAX];
__device__ int   g_rowptr[NMAX];
__device__ int   g_cursor[NMAX];
__device__ int   g_esrc[EMAX];
__device__ int   g_alloc;                        // CSR allocation counter

__device__ __forceinline__ float neg_inf() { return __int_as_float(0xFF800000); }

__device__ __forceinline__ uint32_t pack_bf2(float x, float y) {
    __nv_bfloat162 p = __floats2bfloat162_rn(x, y);   // .x = low half
    return *reinterpret_cast<uint32_t*>(&p);
}

__device__ __forceinline__ void mma_bf16(float* c, const uint32_t* a, const uint32_t* b) {
    asm volatile(
        "mma.sync.aligned.m16n8k16.row.col.f32.bf16.bf16.f32 "
        "{%0,%1,%2,%3},{%4,%5,%6,%7},{%8,%9},{%0,%1,%2,%3};"
        : "+f"(c[0]), "+f"(c[1]), "+f"(c[2]), "+f"(c[3])
        : "r"(a[0]), "r"(a[1]), "r"(a[2]), "r"(a[3]), "r"(b[0]), "r"(b[1]));
}

// ---------------- init: zero deg, reset global sums + alloc ----------------
__global__ void init_kernel(int N) {
    int i = blockIdx.x * blockDim.x + threadIdx.x;
    if (i < N) g_deg[i] = 0;
    if (i == 0) {
        #pragma unroll
        for (int h = 0; h < HEADS_; h++) g_gsum[h] = 0.f;
        g_alloc = 0;
    }
}

// ---------------- W pre-conversion: fp32 [k][n] -> bf16 hi/lo [n][k] -------
__global__ void wconv_kernel(const float* __restrict__ W) {
    int idx = blockIdx.x * blockDim.x + threadIdx.x;
    if (idx >= 128 * 128) return;
    int k = idx >> 7, n = idx & 127;
    float v = W[idx];
    __nv_bfloat16 hi = __float2bfloat16(v);
    float rem = v - __bfloat162float(hi);
    g_WbH[n * 128 + k] = hi;
    g_WbL[n * 128 + k] = __float2bfloat16(rem);
}

// ---------------- degree histogram (4 edges per thread) --------------------
__global__ void count_kernel(const int* __restrict__ ei, int E) {
    int t = blockIdx.x * blockDim.x + threadIdx.x;
    int base = t * 4;
    if (base + 3 < E) {
        int4 d = *(const int4*)(ei + E + base);
        atomicAdd(&g_deg[d.x], 1); atomicAdd(&g_deg[d.y], 1);
        atomicAdd(&g_deg[d.z], 1); atomicAdd(&g_deg[d.w], 1);
    } else {
        for (int e = base; e < E; e++) atomicAdd(&g_deg[ei[E + e]], 1);
    }
}

// ---------------- fused scan: block scan + atomic base allocation ----------
__global__ __launch_bounds__(1024) void scanf_kernel(int N) {
    __shared__ int warp_excl[32];
    __shared__ int s_base;
    int tid = threadIdx.x;
    int lane = tid & 31, w = tid >> 5;
    int i = blockIdx.x * 1024 + tid;
    int d = (i < N) ? g_deg[i] : 0;

    int x = d;
    #pragma unroll
    for (int o = 1; o < 32; o <<= 1) {
        int y = __shfl_up_sync(0xFFFFFFFFu, x, o);
        if (lane >= o) x += y;
    }
    if (lane == 31) warp_excl[w] = x;     // warp totals
    __syncthreads();
    if (w == 0) {
        int v = warp_excl[lane];
        int xx = v;
        #pragma unroll
        for (int o = 1; o < 32; o <<= 1) {
            int y = __shfl_up_sync(0xFFFFFFFFu, xx, o);
            if (lane >= o) xx += y;
        }
        warp_excl[lane] = xx - v;          // exclusive warp offsets
        if (lane == 31) s_base = atomicAdd(&g_alloc, xx);  // block base
    }
    __syncthreads();
    if (i < N) {
        int start = s_base + warp_excl[w] + (x - d);
        g_rowptr[i] = start;
        g_cursor[i] = start;
    }
}

// ---------------- scatter src ids into CSR order ---------------------------
__global__ void scatter_kernel(const int* __restrict__ ei, int E) {
    int e = blockIdx.x * blockDim.x + threadIdx.x;
    if (e >= E) return;
    int src = ei[e];
    int dst = ei[E + e];
    int pos = atomicAdd(&g_cursor[dst], 1);
    g_esrc[pos] = src;
}

// ---------------- 3x bf16 m16n8k16 GEMM, double-buffered (R13 layout) ------
__global__ __launch_bounds__(256, 2) void gemm_kernel(
    const float* __restrict__ A, const float* __restrict__ av_g, int N)
{
    __shared__ uint32_t AsH[2][128 * 12];
    __shared__ uint32_t AsL[2][128 * 12];
    __shared__ uint32_t BsH[2][128 * 12];
    __shared__ uint32_t BsL[2][128 * 12];
    __shared__ float sA[256];       // attention vector a: [head][src32|dst32]

    int tid = threadIdx.x;
    int lane = tid & 31, wid = tid >> 5;
    int g = lane >> 2, t = lane & 3;
    int wm = (wid & 3) * 32;
    int wn = (wid >> 2) * 64;
    int br = blockIdx.x * 128;

    sA[tid] = av_g[tid];

    int arow = tid >> 1;            // 0..127
    int ak   = (tid & 1) * 8;       // k offset within 16-tile: 0 or 8
    int bn_  = tid >> 1;            // B n row
    int bkof = (tid & 1) * 8;
    int grow = br + arow;
    bool arok = grow < N;

    float c[2][8][4];
    #pragma unroll
    for (int mt = 0; mt < 2; mt++)
        #pragma unroll
        for (int nt = 0; nt < 8; nt++)
            #pragma unroll
            for (int q = 0; q < 4; q++) c[mt][nt][q] = 0.f;

    auto load_a = [&](int k0, float* av) {
        av[0]=av[1]=av[2]=av[3]=av[4]=av[5]=av[6]=av[7]=0.f;
        if (arok) {
            float4 a0 = *(const float4*)(A + (size_t)grow * INF_ + k0 + ak);
            float4 a1 = *(const float4*)(A + (size_t)grow * INF_ + k0 + ak + 4);
            av[0] = a0.x; av[1] = a0.y; av[2] = a0.z; av[3] = a0.w;
            av[4] = a1.x; av[5] = a1.y; av[6] = a1.z; av[7] = a1.w;
        }
    };
    auto store_tile = [&](int buf, const float* av, uint4 wbh, uint4 wbl) {
        uint32_t hw[4], lw[4];
        #pragma unroll
        for (int j = 0; j < 4; j++) {
            float x = av[2 * j], y = av[2 * j + 1];
            __nv_bfloat16 xh = __float2bfloat16(x);
            __nv_bfloat16 yh = __float2bfloat16(y);
            float xr = x - __bfloat162float(xh);
            float yr = y - __bfloat162float(yh);
            __nv_bfloat162 ph; ph.x = xh; ph.y = yh;
            hw[j] = *reinterpret_cast<uint32_t*>(&ph);
            lw[j] = pack_bf2(xr, yr);
        }
        *(uint4*)&AsH[buf][arow * 12 + (ak >> 1)] = make_uint4(hw[0], hw[1], hw[2], hw[3]);
        *(uint4*)&AsL[buf][arow * 12 + (ak >> 1)] = make_uint4(lw[0], lw[1], lw[2], lw[3]);
        *(uint4*)&BsH[buf][bn_ * 12 + (bkof >> 1)] = wbh;
        *(uint4*)&BsL[buf][bn_ * 12 + (bkof >> 1)] = wbl;
    };

    // ---- prologue: tile 0 ----
    {
        float av[8];
        load_a(0, av);
        uint4 wbh = *(const uint4*)(g_WbH + (size_t)bn_ * 128 + bkof);
        uint4 wbl = *(const uint4*)(g_WbL + (size_t)bn_ * 128 + bkof);
        store_tile(0, av, wbh, wbl);
    }
    __syncthreads();

    // ---- main loop: 8 K-tiles, double-buffered ----
    #pragma unroll
    for (int kt = 0; kt < 8; kt++) {
        int cur = kt & 1;
        float av2[8];
        uint4 nbh, nbl;
        if (kt < 7) {
            int k0 = (kt + 1) * 16;
            load_a(k0, av2);
            nbh = *(const uint4*)(g_WbH + (size_t)bn_ * 128 + k0 + bkof);
            nbl = *(const uint4*)(g_WbL + (size_t)bn_ * 128 + k0 + bkof);
        }

        uint32_t afh[2][4], afl[2][4];
        #pragma unroll
        for (int mt = 0; mt < 2; mt++) {
            int m0 = (wm + mt * 16 + g) * 12;
            int m1 = (wm + mt * 16 + g + 8) * 12;
            afh[mt][0] = AsH[cur][m0 + t];     afh[mt][1] = AsH[cur][m1 + t];
            afh[mt][2] = AsH[cur][m0 + t + 4]; afh[mt][3] = AsH[cur][m1 + t + 4];
            afl[mt][0] = AsL[cur][m0 + t];     afl[mt][1] = AsL[cur][m1 + t];
            afl[mt][2] = AsL[cur][m0 + t + 4]; afl[mt][3] = AsL[cur][m1 + t + 4];
        }
        #pragma unroll
        for (int nt = 0; nt < 8; nt++) {
            int nb = (wn + nt * 8 + g) * 12;
            uint32_t bfh[2], bfl[2];
            bfh[0] = BsH[cur][nb + t]; bfh[1] = BsH[cur][nb + t + 4];
            bfl[0] = BsL[cur][nb + t]; bfl[1] = BsL[cur][nb + t + 4];
            #pragma unroll
            for (int mt = 0; mt < 2; mt++) {
                mma_bf16(c[mt][nt], afl[mt], bfh);   // lo*hi
                mma_bf16(c[mt][nt], afh[mt], bfl);   // hi*lo
                mma_bf16(c[mt][nt], afh[mt], bfh);   // hi*hi
            }
        }

        if (kt < 7) {
            store_tile(cur ^ 1, av2, nbh, nbl);
            __syncthreads();
        }
    }

    // ---- store Wh as fp16 (only consumer is the aggregate gather) ----
    #pragma unroll
    for (int mt = 0; mt < 2; mt++) {
        #pragma unroll
        for (int nt = 0; nt < 8; nt++) {
            int row0 = br + wm + mt * 16 + g;
            int col = wn + nt * 8 + 2 * t;
            if (row0 < N)
                *(__half2*)(g_WhH + (size_t)row0 * OC_ + col) =
                    __floats2half2_rn(c[mt][nt][0], c[mt][nt][1]);
            int row1 = row0 + 8;
            if (row1 < N)
                *(__half2*)(g_WhH + (size_t)row1 * OC_ + col) =
                    __floats2half2_rn(c[mt][nt][2], c[mt][nt][3]);
        }
    }

    // ---- fused scores from register fragments (fp32) ----
    float ds[2][2][2] = {}, dd[2][2][2] = {};
    #pragma unroll
    for (int nt = 0; nt < 8; nt++) {
        int col0 = wn + nt * 8 + 2 * t;
        int hgl = col0 >> 5;
        int j = col0 & 31;
        float as0 = sA[hgl * 64 + j],      as1 = sA[hgl * 64 + j + 1];
        float ad0 = sA[hgl * 64 + 32 + j], ad1 = sA[hgl * 64 + 33 + j];
        int hh = nt >> 2;
        #pragma unroll
        for (int mt = 0; mt < 2; mt++) {
            ds[mt][0][hh] += c[mt][nt][0] * as0 + c[mt][nt][1] * as1;
            ds[mt][1][hh] += c[mt][nt][2] * as0 + c[mt][nt][3] * as1;
            dd[mt][0][hh] += c[mt][nt][0] * ad0 + c[mt][nt][1] * ad1;
            dd[mt][1][hh] += c[mt][nt][2] * ad0 + c[mt][nt][3] * ad1;
        }
    }
    int hbase = wn >> 5;
    #pragma unroll
    for (int mt = 0; mt < 2; mt++)
        #pragma unroll
        for (int rh = 0; rh < 2; rh++)
            #pragma unroll
            for (int hh = 0; hh < 2; hh++) {
                float vs = ds[mt][rh][hh];
                float vd = dd[mt][rh][hh];
                vs += __shfl_xor_sync(0xFFFFFFFFu, vs, 1);
                vs += __shfl_xor_sync(0xFFFFFFFFu, vs, 2);
                vd += __shfl_xor_sync(0xFFFFFFFFu, vd, 1);
                vd += __shfl_xor_sync(0xFFFFFFFFu, vd, 2);
                if (t == 0) {
                    int row = br + wm + mt * 16 + g + rh * 8;
                    if (row < N) {
                        g_ssrc[row * HEADS_ + hbase + hh] = vs;
                        g_sdst[row * HEADS_ + hbase + hh] = vd;
                    }
                }
            }
}

// ---------------- pull segment-max + leaky + exp + global sum --------------
__global__ __launch_bounds__(256) void nodemax_kernel(int N) {
    __shared__ float ssum[8][4];
    int gw   = (blockIdx.x * blockDim.x + threadIdx.x) >> 5;
    int lane = threadIdx.x & 31;
    int wrp  = threadIdx.x >> 5;
    bool valid = gw < N;

    float ni = neg_inf();
    float e0 = 0.f, e1 = 0.f, e2 = 0.f, e3 = 0.f;
    if (valid) {
        int start = g_rowptr[gw];
        int cnt   = g_deg[gw];
        float m0 = ni, m1 = ni, m2 = ni, m3 = ni;
        for (int i = lane; i < cnt; i += 32) {
            int s = g_esrc[start + i];
            float4 v = *(const float4*)(g_ssrc + (size_t)s * HEADS_);
            m0 = fmaxf(m0, v.x); m1 = fmaxf(m1, v.y);
            m2 = fmaxf(m2, v.z); m3 = fmaxf(m3, v.w);
        }
        #pragma unroll
        for (int o = 16; o >= 1; o >>= 1) {
            m0 = fmaxf(m0, __shfl_xor_sync(0xFFFFFFFFu, m0, o));
            m1 = fmaxf(m1, __shfl_xor_sync(0xFFFFFFFFu, m1, o));
            m2 = fmaxf(m2, __shfl_xor_sync(0xFFFFFFFFu, m2, o));
            m3 = fmaxf(m3, __shfl_xor_sync(0xFFFFFFFFu, m3, o));
        }
        if (lane == 0) {
            float4 sd = *(const float4*)(g_sdst + (size_t)gw * HEADS_);
            float v0 = m0 + sd.x; v0 = v0 > 0.f ? v0 : NEG_SLOPE_ * v0;
            float v1 = m1 + sd.y; v1 = v1 > 0.f ? v1 : NEG_SLOPE_ * v1;
            float v2 = m2 + sd.z; v2 = v2 > 0.f ? v2 : NEG_SLOPE_ * v2;
            float v3 = m3 + sd.w; v3 = v3 > 0.f ? v3 : NEG_SLOPE_ * v3;
            e0 = __expf(v0); e1 = __expf(v1);
            e2 = __expf(v2); e3 = __expf(v3);
            *(float4*)(g_attn + (size_t)gw * HEADS_) = make_float4(e0, e1, e2, e3);
        }
    }
    if (lane == 0) {
        ssum[wrp][0] = e0; ssum[wrp][1] = e1;
        ssum[wrp][2] = e2; ssum[wrp][3] = e3;
    }
    __syncthreads();
    if (threadIdx.x < 4) {
        float s = ssum[0][threadIdx.x];
        #pragma unroll
        for (int w = 1; w < 8; w++) s += ssum[w][threadIdx.x];
        atomicAdd(&g_gsum[threadIdx.x], s);
    }
}

// ---------------- pull aggregation (fp16 gather, fp32 accumulate) ----------
__global__ __launch_bounds__(256) void aggregate_kernel(float* __restrict__ out, int N) {
    int gw   = (blockIdx.x * blockDim.x + threadIdx.x) >> 5;
    int lane = threadIdx.x & 31;
    if (gw >= N) return;
    int start = g_rowptr[gw];
    int end   = start + g_deg[gw];

    float ax = 0.f, ay = 0.f, az = 0.f, aw = 0.f;
    const __half* whl = g_WhH + lane * 4;   // lane covers cols [lane*4, lane*4+4)
    int i = start;
    for (; i + 7 < end; i += 8) {
        uint2 u0 = *(const uint2*)(whl + (size_t)g_esrc[i + 0] * OC_);
        uint2 u1 = *(const uint2*)(whl + (size_t)g_esrc[i + 1] * OC_);
        uint2 u2 = *(const uint2*)(whl + (size_t)g_esrc[i + 2] * OC_);
        uint2 u3 = *(const uint2*)(whl + (size_t)g_esrc[i + 3] * OC_);
        uint2 u4 = *(const uint2*)(whl + (size_t)g_esrc[i + 4] * OC_);
        uint2 u5 = *(const uint2*)(whl + (size_t)g_esrc[i + 5] * OC_);
        uint2 u6 = *(const uint2*)(whl + (size_t)g_esrc[i + 6] * OC_);
        uint2 u7 = *(const uint2*)(whl + (size_t)g_esrc[i + 7] * OC_);
        float2 a0 = __half22float2(*(__half2*)&u0.x), b0 = __half22float2(*(__half2*)&u0.y);
        float2 a1 = __half22float2(*(__half2*)&u1.x), b1 = __half22float2(*(__half2*)&u1.y);
        float2 a2 = __half22float2(*(__half2*)&u2.x), b2 = __half22float2(*(__half2*)&u2.y);
        float2 a3 = __half22float2(*(__half2*)&u3.x), b3 = __half22float2(*(__half2*)&u3.y);
        float2 a4 = __half22float2(*(__half2*)&u4.x), b4 = __half22float2(*(__half2*)&u4.y);
        float2 a5 = __half22float2(*(__half2*)&u5.x), b5 = __half22float2(*(__half2*)&u5.y);
        float2 a6 = __half22float2(*(__half2*)&u6.x), b6 = __half22float2(*(__half2*)&u6.y);
        float2 a7 = __half22float2(*(__half2*)&u7.x), b7 = __half22float2(*(__half2*)&u7.y);
        ax += (a0.x + a1.x) + (a2.x + a3.x) + ((a4.x + a5.x) + (a6.x + a7.x));
        ay += (a0.y + a1.y) + (a2.y + a3.y) + ((a4.y + a5.y) + (a6.y + a7.y));
        az += (b0.x + b1.x) + (b2.x + b3.x) + ((b4.x + b5.x) + (b6.x + b7.x));
        aw += (b0.y + b1.y) + (b2.y + b3.y) + ((b4.y + b5.y) + (b6.y + b7.y));
    }
    for (; i < end; i++) {
        uint2 u = *(const uint2*)(whl + (size_t)g_esrc[i] * OC_);
        float2 a = __half22float2(*(__half2*)&u.x), b = __half22float2(*(__half2*)&u.y);
        ax += a.x; ay += a.y; az += b.x; aw += b.y;
    }

    int head = lane >> 3;
    float attn = g_attn[(size_t)gw * HEADS_ + head] / g_gsum[head];
    *(float4*)(out + (size_t)gw * OC_ + lane * 4) =
        make_float4(ax * attn, ay * attn, az * attn, aw * attn);
}

// ---------------- launch: gemm kept at submission index 3 for ncu ----------
extern "C" void kernel_launch(void* const* d_in, const int* in_sizes, int n_in,
                              void* d_out, int out_size) {
    const float* h  = (const float*)d_in[0];
    const int*   ei = (const int*)d_in[1];
    const float* W  = (const float*)d_in[2];
    const float* a  = (const float*)d_in[3];
    float* out = (float*)d_out;

    int N = in_sizes[0] / INF_;
    int E = in_sizes[1] / 2;
    int nb = (N + 1023) / 1024;

    static cudaStream_t s2 = nullptr;
    static cudaEvent_t e0 = nullptr, e2 = nullptr;
    if (s2 == nullptr) {
        cudaStreamCreateWithFlags(&s2, cudaStreamNonBlocking);
        cudaEventCreateWithFlags(&e0, cudaEventDisableTiming);
        cudaEventCreateWithFlags(&e2, cudaEventDisableTiming);
    }

    // fork: CSR build chain on s2; W conversion + GEMM on the main stream
    cudaEventRecord(e0, 0);
    cudaStreamWaitEvent(s2, e0, 0);

    // submission 0: W hi/lo pre-conversion (main stream, before gemm)
    wconv_kernel<<<64, 256>>>(W);
    // submissions 1-2 (CSR head on s2)
    init_kernel<<<(N + 255) / 256, 256, 0, s2>>>(N);
    count_kernel<<<((E + 3) / 4 + 255) / 256, 256, 0, s2>>>(ei, E);
    // submission 3: gemm (ncu capture target)
    gemm_kernel<<<(N + 127) / 128, 256>>>(h, a, N);
    // CSR tail on s2 (fused scan + scatter)
    scanf_kernel<<<nb, 1024, 0, s2>>>(N);
    scatter_kernel<<<(E + 255) / 256, 256, 0, s2>>>(ei, E);
    cudaEventRecord(e2, s2);

    // join: nodemax needs CSR + scores
    cudaStreamWaitEvent(0, e2, 0);

    nodemax_kernel<<<(N * 32 + 255) / 256, 256>>>(N);
    aggregate_kernel<<<(N * 32 + 255) / 256, 256>>>(out, N);
}